// round 3
// baseline (speedup 1.0000x reference)
#include <cuda_runtime.h>

// ---------------------------------------------------------------------------
// 2-layer GCN: out = gcn(relu(gcn(x, W1, b1)), W2, b2)
// gcn(h) = D^-1/2 (A+I) D^-1/2 (h @ W) + b, deg counted over dst incl. self.
//
// Strategy:
//   g = (h @ W) * dinv[row]           (dinv folded into GEMM epilogue)
//   agg[d] = dinv[d] * (sum_{in-edges} g[src] + g[d])   (self-loop = own row)
// Pull-based aggregation over a CSR-by-dst built per call (no float atomics).
//
// edge_index dtype is probed at runtime (int32 vs int64) -- see k_detect.
// ---------------------------------------------------------------------------

#define MAXN 100000
#define MAXE 1600000

__device__ int   d_mode;               // 0 = int32 edge_index, 1 = int64
__device__ int   d_counts[MAXN];
__device__ int   d_cursor[MAXN];
__device__ int   d_rowptr[MAXN + 1];
__device__ int   d_col[MAXE];
__device__ float d_dinv[MAXN];
__device__ float d_g1[MAXN * 128];     // (x@W1)*dinv
__device__ float d_out1[MAXN * 128];   // relu(layer1)
__device__ float d_g2[MAXN * 16];      // (out1@W2)*dinv
__device__ int   d_bsums[128];

// ---------------- dtype probe ----------------
// int64 indices < 2^31 have zero high words at every odd 32-bit position.

__global__ void k_detect(const unsigned* __restrict__ ei_w) {
    if (threadIdx.x == 0) {
        int odd_nonzero = 0;
        #pragma unroll 1
        for (int i = 1; i < 512; i += 2)
            if (ei_w[i] != 0u) odd_nonzero++;
        d_mode = (odd_nonzero == 0) ? 1 : 0;
    }
}

__device__ __forceinline__ int load_idx(const void* ei, int e, int which, int i) {
    // which: 0 = src row, 1 = dst row
    if (d_mode) {
        long long v = ((const long long*)ei)[(long long)which * e + i];
        return (int)v;
    } else {
        return ((const int*)ei)[which * e + i];
    }
}

// ---------------- CSR build ----------------

__global__ void k_zero(int n) {
    int i = blockIdx.x * blockDim.x + threadIdx.x;
    if (i < n) { d_counts[i] = 0; d_cursor[i] = 0; }
}

__global__ void k_deg(const void* __restrict__ ei, int e, int n) {
    int i = blockIdx.x * blockDim.x + threadIdx.x;
    if (i < e) {
        int d = load_idx(ei, e, 1, i);
        if ((unsigned)d < (unsigned)n) atomicAdd(&d_counts[d], 1);
    }
}

__global__ void k_dinv(int n) {
    int i = blockIdx.x * blockDim.x + threadIdx.x;
    if (i < n) d_dinv[i] = rsqrtf((float)(d_counts[i] + 1));
}

__global__ void k_scan1(int n) {
    __shared__ int s[1024];
    int t = threadIdx.x;
    int i = blockIdx.x * 1024 + t;
    int v = (i < n) ? d_counts[i] : 0;
    s[t] = v;
    __syncthreads();
    for (int off = 1; off < 1024; off <<= 1) {
        int a = (t >= off) ? s[t - off] : 0;
        __syncthreads();
        s[t] += a;
        __syncthreads();
    }
    if (i < n) d_rowptr[i] = s[t] - v;               // exclusive within block
    if (t == 1023) d_bsums[blockIdx.x] = s[t];       // block total
}

__global__ void k_scan2(int nb) {
    __shared__ int s[128];
    int t = threadIdx.x;
    int v = (t < nb) ? d_bsums[t] : 0;
    s[t] = v;
    __syncthreads();
    for (int off = 1; off < 128; off <<= 1) {
        int a = (t >= off) ? s[t - off] : 0;
        __syncthreads();
        s[t] += a;
        __syncthreads();
    }
    if (t < nb) d_bsums[t] = s[t] - v;               // exclusive block offsets
}

__global__ void k_scan3(int n, int e) {
    int t = threadIdx.x;
    int i = blockIdx.x * 1024 + t;
    if (i < n) d_rowptr[i] += d_bsums[blockIdx.x];
    if (i == 0) d_rowptr[n] = e;
}

__global__ void k_fill(const void* __restrict__ ei, int e, int n) {
    int i = blockIdx.x * blockDim.x + threadIdx.x;
    if (i < e) {
        int s = load_idx(ei, e, 0, i);
        int d = load_idx(ei, e, 1, i);
        if ((unsigned)d < (unsigned)n && (unsigned)s < (unsigned)n) {
            int pos = d_rowptr[d] + atomicAdd(&d_cursor[d], 1);
            d_col[pos] = s;
        }
    }
}

// ---------------- Layer 1 GEMM: g1 = (x @ W1) * dinv ----------------
// Block: 32 rows x 128 cols, 256 threads, 4x4 micro-tile per thread.

__global__ __launch_bounds__(256) void k_gemm1(const float* __restrict__ x,
                                               const float* __restrict__ W1,
                                               int n) {
    __shared__ float xs[32][33];
    __shared__ float ws[32][128];
    int tid = threadIdx.x;
    int row0 = blockIdx.x * 32;
    int tx = tid & 31;   // col group: cols tx*4 .. tx*4+3
    int ty = tid >> 5;   // row group: rows ty*4 .. ty*4+3
    float acc[4][4] = {};

    for (int k0 = 0; k0 < 256; k0 += 32) {
        // load x tile [32 rows][32 k]
        {
            int r = tid >> 3;
            int c = (tid & 7) * 4;
            if (row0 + r < n) {
                float4 v = *(const float4*)&x[(row0 + r) * 256 + k0 + c];
                xs[r][c] = v.x; xs[r][c + 1] = v.y; xs[r][c + 2] = v.z; xs[r][c + 3] = v.w;
            } else {
                xs[r][c] = 0.f; xs[r][c + 1] = 0.f; xs[r][c + 2] = 0.f; xs[r][c + 3] = 0.f;
            }
        }
        // load W1 tile [32 k][128 cols]
        #pragma unroll
        for (int i2 = 0; i2 < 4; i2++) {
            int f4 = tid + i2 * 256;       // 1024 float4s total
            int kk = f4 >> 5;
            int c  = (f4 & 31) * 4;
            *(float4*)&ws[kk][c] = *(const float4*)&W1[(k0 + kk) * 128 + c];
        }
        __syncthreads();
        #pragma unroll
        for (int kk = 0; kk < 32; kk++) {
            float4 b = *(float4*)&ws[kk][tx * 4];
            #pragma unroll
            for (int r = 0; r < 4; r++) {
                float a = xs[ty * 4 + r][kk];
                acc[r][0] += a * b.x;
                acc[r][1] += a * b.y;
                acc[r][2] += a * b.z;
                acc[r][3] += a * b.w;
            }
        }
        __syncthreads();
    }
    #pragma unroll
    for (int r = 0; r < 4; r++) {
        int row = row0 + ty * 4 + r;
        if (row < n) {
            float sc = d_dinv[row];
            float4 o;
            o.x = acc[r][0] * sc; o.y = acc[r][1] * sc;
            o.z = acc[r][2] * sc; o.w = acc[r][3] * sc;
            *(float4*)&d_g1[row * 128 + tx * 4] = o;
        }
    }
}

// ---------------- Layer 1 aggregation: one warp per node ----------------

__global__ __launch_bounds__(256) void k_agg1(const float* __restrict__ b1, int n) {
    int w = (blockIdx.x * 256 + threadIdx.x) >> 5;
    int lane = threadIdx.x & 31;
    if (w >= n) return;
    const float4* g1 = (const float4*)d_g1;
    float4 acc = g1[w * 32 + lane];     // self-loop contribution
    int e = d_rowptr[w], end = d_rowptr[w + 1];
    for (; e + 4 <= end; e += 4) {
        int s0 = d_col[e], s1 = d_col[e + 1], s2 = d_col[e + 2], s3 = d_col[e + 3];
        float4 v0 = g1[s0 * 32 + lane];
        float4 v1 = g1[s1 * 32 + lane];
        float4 v2 = g1[s2 * 32 + lane];
        float4 v3 = g1[s3 * 32 + lane];
        acc.x += (v0.x + v1.x) + (v2.x + v3.x);
        acc.y += (v0.y + v1.y) + (v2.y + v3.y);
        acc.z += (v0.z + v1.z) + (v2.z + v3.z);
        acc.w += (v0.w + v1.w) + (v2.w + v3.w);
    }
    for (; e < end; e++) {
        int s = d_col[e];
        float4 v = g1[s * 32 + lane];
        acc.x += v.x; acc.y += v.y; acc.z += v.z; acc.w += v.w;
    }
    float sc = d_dinv[w];
    float4 bb = ((const float4*)b1)[lane];
    float4 o;
    o.x = fmaxf(fmaf(sc, acc.x, bb.x), 0.f);
    o.y = fmaxf(fmaf(sc, acc.y, bb.y), 0.f);
    o.z = fmaxf(fmaf(sc, acc.z, bb.z), 0.f);
    o.w = fmaxf(fmaf(sc, acc.w, bb.w), 0.f);
    ((float4*)d_out1)[w * 32 + lane] = o;
}

// ---------------- Layer 2 GEMM: g2 = (out1 @ W2) * dinv ----------------
// 4 threads per row, each computes 4 of 16 output cols.

__global__ __launch_bounds__(256) void k_gemm2(const float* __restrict__ W2, int n) {
    int t = blockIdx.x * blockDim.x + threadIdx.x;
    int row = t >> 2;
    int part = t & 3;
    if (row >= n) return;
    const float4* h = (const float4*)(d_out1 + row * 128);
    const float4* w = (const float4*)W2;   // W2[128][16] -> float4 index k*4+part
    float4 acc = make_float4(0.f, 0.f, 0.f, 0.f);
    #pragma unroll
    for (int k4 = 0; k4 < 32; k4++) {
        float4 a = h[k4];
        float4 w0 = w[(k4 * 4 + 0) * 4 + part];
        float4 w1 = w[(k4 * 4 + 1) * 4 + part];
        float4 w2v = w[(k4 * 4 + 2) * 4 + part];
        float4 w3 = w[(k4 * 4 + 3) * 4 + part];
        acc.x += a.x * w0.x + a.y * w1.x + a.z * w2v.x + a.w * w3.x;
        acc.y += a.x * w0.y + a.y * w1.y + a.z * w2v.y + a.w * w3.y;
        acc.z += a.x * w0.z + a.y * w1.z + a.z * w2v.z + a.w * w3.z;
        acc.w += a.x * w0.w + a.y * w1.w + a.z * w2v.w + a.w * w3.w;
    }
    float sc = d_dinv[row];
    float4 o = make_float4(acc.x * sc, acc.y * sc, acc.z * sc, acc.w * sc);
    ((float4*)d_g2)[row * 4 + part] = o;
}

// ---------------- Layer 2 aggregation + final output ----------------

__global__ __launch_bounds__(256) void k_agg2(const float* __restrict__ b2,
                                              float* __restrict__ out, int n) {
    int t = blockIdx.x * blockDim.x + threadIdx.x;
    int row = t >> 2;
    int part = t & 3;
    if (row >= n) return;
    const float4* g2 = (const float4*)d_g2;
    float4 acc = g2[row * 4 + part];    // self-loop
    int e = d_rowptr[row], end = d_rowptr[row + 1];
    for (; e + 4 <= end; e += 4) {
        int s0 = d_col[e], s1 = d_col[e + 1], s2 = d_col[e + 2], s3 = d_col[e + 3];
        float4 v0 = g2[s0 * 4 + part];
        float4 v1 = g2[s1 * 4 + part];
        float4 v2 = g2[s2 * 4 + part];
        float4 v3 = g2[s3 * 4 + part];
        acc.x += (v0.x + v1.x) + (v2.x + v3.x);
        acc.y += (v0.y + v1.y) + (v2.y + v3.y);
        acc.z += (v0.z + v1.z) + (v2.z + v3.z);
        acc.w += (v0.w + v1.w) + (v2.w + v3.w);
    }
    for (; e < end; e++) {
        int s = d_col[e];
        float4 v = g2[s * 4 + part];
        acc.x += v.x; acc.y += v.y; acc.z += v.z; acc.w += v.w;
    }
    float sc = d_dinv[row];
    float4 bb = ((const float4*)b2)[part];
    float4 o;
    o.x = fmaf(sc, acc.x, bb.x);
    o.y = fmaf(sc, acc.y, bb.y);
    o.z = fmaf(sc, acc.z, bb.z);
    o.w = fmaf(sc, acc.w, bb.w);
    *(float4*)&out[row * 16 + part * 4] = o;
}

// ---------------- launch ----------------

extern "C" void kernel_launch(void* const* d_in, const int* in_sizes, int n_in,
                              void* d_out, int out_size) {
    const float* x  = (const float*)d_in[0];
    const void*  ei = d_in[1];                 // int32 or int64; probed on device
    const float* W1 = (const float*)d_in[2];
    const float* b1 = (const float*)d_in[3];
    const float* W2 = (const float*)d_in[4];
    const float* b2 = (const float*)d_in[5];
    float* out = (float*)d_out;

    int n = in_sizes[0] / 256;
    int e = in_sizes[1] / 2;
    int nb_scan = (n + 1023) / 1024;

    k_detect<<<1, 32>>>((const unsigned*)ei);
    k_zero <<<(n + 255) / 256, 256>>>(n);
    k_deg  <<<(e + 255) / 256, 256>>>(ei, e, n);
    k_dinv <<<(n + 255) / 256, 256>>>(n);
    k_scan1<<<nb_scan, 1024>>>(n);
    k_scan2<<<1, 128>>>(nb_scan);
    k_scan3<<<nb_scan, 1024>>>(n, e);
    k_fill <<<(e + 255) / 256, 256>>>(ei, e, n);

    k_gemm1<<<(n + 31) / 32, 256>>>(x, W1, n);
    k_agg1 <<<(n * 32 + 255) / 256, 256>>>(b1, n);
    k_gemm2<<<(n * 4 + 255) / 256, 256>>>(W2, n);
    k_agg2 <<<(n * 4 + 255) / 256, 256>>>(b2, out, n);
}

// round 5
// speedup vs baseline: 1.6522x; 1.6522x over previous
#include <cuda_runtime.h>

// ---------------------------------------------------------------------------
// 2-layer GCN: out = gcn(relu(gcn(x, W1, b1)), W2, b2)
//   g = (h @ W) * dinv[row]         (dinv folded into GEMM epilogue)
//   agg[d] = dinv[d] * (sum_in g[src] + g[d])  (self-loop = own row)
// Pull aggregation over per-call CSR-by-dst. GEMM1 on tensor cores (tf32).
// edge_index dtype probed at runtime (int32 vs int64).
// ---------------------------------------------------------------------------

#define MAXN 100000
#define MAXE 1600000

__device__ int   d_mode;
__device__ int   d_counts[MAXN];
__device__ int   d_cursor[MAXN];
__device__ int   d_rowptr[MAXN + 1];
__device__ int   d_col[MAXE];
__device__ float d_dinv[MAXN];
__device__ float d_g1[MAXN * 128];
__device__ float d_out1[MAXN * 128];
__device__ float d_g2[MAXN * 16];
__device__ int   d_bsums[128];

// ---------------- dtype probe (warp-parallel) ----------------

__global__ void k_detect(const unsigned* __restrict__ ei_w) {
    int l = threadIdx.x;
    unsigned any = 0;
    #pragma unroll
    for (int i = 0; i < 8; i++) any |= ei_w[2 * (l + i * 32) + 1];
    unsigned ball = __ballot_sync(0xFFFFFFFFu, any != 0);
    if (l == 0) d_mode = (ball == 0) ? 1 : 0;
}

__device__ __forceinline__ int load_idx(const void* ei, int e, int which, int i) {
    if (d_mode) return (int)((const long long*)ei)[(long long)which * e + i];
    return ((const int*)ei)[which * e + i];
}

// ---------------- CSR build ----------------

__global__ void k_zero(int n) {
    int i = blockIdx.x * blockDim.x + threadIdx.x;
    if (i < n) { d_counts[i] = 0; d_cursor[i] = 0; }
}

__global__ void k_deg(const void* __restrict__ ei, int e, int n) {
    int i = blockIdx.x * blockDim.x + threadIdx.x;
    if (i < e) {
        int d = load_idx(ei, e, 1, i);
        if ((unsigned)d < (unsigned)n) atomicAdd(&d_counts[d], 1);
    }
}

__global__ void k_scan1(int n) {
    __shared__ int s[1024];
    int t = threadIdx.x;
    int i = blockIdx.x * 1024 + t;
    int v = (i < n) ? d_counts[i] : 0;
    if (i < n) d_dinv[i] = rsqrtf((float)(v + 1));   // fused dinv
    s[t] = v;
    __syncthreads();
    for (int off = 1; off < 1024; off <<= 1) {
        int a = (t >= off) ? s[t - off] : 0;
        __syncthreads();
        s[t] += a;
        __syncthreads();
    }
    if (i < n) d_rowptr[i] = s[t] - v;
    if (t == 1023) d_bsums[blockIdx.x] = s[t];
}

__global__ void k_scan2(int nb) {
    __shared__ int s[128];
    int t = threadIdx.x;
    int v = (t < nb) ? d_bsums[t] : 0;
    s[t] = v;
    __syncthreads();
    for (int off = 1; off < 128; off <<= 1) {
        int a = (t >= off) ? s[t - off] : 0;
        __syncthreads();
        s[t] += a;
        __syncthreads();
    }
    if (t < nb) d_bsums[t] = s[t] - v;
}

__global__ void k_scan3(int n, int e) {
    int t = threadIdx.x;
    int i = blockIdx.x * 1024 + t;
    if (i < n) d_rowptr[i] += d_bsums[blockIdx.x];
    if (i == 0) d_rowptr[n] = e;
}

__global__ void k_fill(const void* __restrict__ ei, int e, int n) {
    int i = blockIdx.x * blockDim.x + threadIdx.x;
    if (i < e) {
        int s = load_idx(ei, e, 0, i);
        int d = load_idx(ei, e, 1, i);
        if ((unsigned)d < (unsigned)n && (unsigned)s < (unsigned)n) {
            int pos = d_rowptr[d] + atomicAdd(&d_cursor[d], 1);
            d_col[pos] = s;
        }
    }
}

// ---------------- Layer 1 GEMM (tensor cores, tf32) ----------------
// Block tile 128x128, 8 warps (2x4), warp tile 64x32, mma.m16n8k8.tf32.

__device__ __forceinline__ unsigned f2tf(float f) {
    unsigned u;
    asm("cvt.rna.tf32.f32 %0, %1;" : "=r"(u) : "f"(f));
    return u;
}

__device__ __forceinline__ void mma_tf32(float* d, const unsigned* a, const unsigned* b) {
    asm volatile(
        "mma.sync.aligned.m16n8k8.row.col.f32.tf32.tf32.f32 "
        "{%0,%1,%2,%3}, {%4,%5,%6,%7}, {%8,%9}, {%0,%1,%2,%3};"
        : "+f"(d[0]), "+f"(d[1]), "+f"(d[2]), "+f"(d[3])
        : "r"(a[0]), "r"(a[1]), "r"(a[2]), "r"(a[3]), "r"(b[0]), "r"(b[1]));
}

__global__ __launch_bounds__(256) void k_gemm1_tc(const float* __restrict__ x,
                                                  const float* __restrict__ W1,
                                                  int n) {
    __shared__ float xs[128][36];    // pad 36: conflict-free frag loads
    __shared__ float ws[32][136];    // pad 136: conflict-free frag loads
    int tid = threadIdx.x;
    int lane = tid & 31;
    int wid = tid >> 5;
    int wm = wid & 1;                // 0..1: 64-row halves
    int wn = wid >> 1;               // 0..3: 32-col quarters
    int row0 = blockIdx.x * 128;

    float acc[4][4][4];
    #pragma unroll
    for (int i = 0; i < 4; i++)
        #pragma unroll
        for (int j = 0; j < 4; j++)
            #pragma unroll
            for (int r = 0; r < 4; r++) acc[i][j][r] = 0.f;

    for (int k0 = 0; k0 < 256; k0 += 32) {
        if (k0) __syncthreads();
        // stage x tile [128 rows][32 k]
        #pragma unroll
        for (int i = 0; i < 4; i++) {
            int f = tid + i * 256;
            int r = f >> 3;
            int c = (f & 7) * 4;
            float4 v = make_float4(0.f, 0.f, 0.f, 0.f);
            if (row0 + r < n) v = *(const float4*)&x[(row0 + r) * 256 + k0 + c];
            xs[r][c] = v.x; xs[r][c + 1] = v.y; xs[r][c + 2] = v.z; xs[r][c + 3] = v.w;
        }
        // stage W1 tile [32 k][128 cols]
        #pragma unroll
        for (int i = 0; i < 4; i++) {
            int f = tid + i * 256;
            int kk = f >> 5;
            int c = (f & 31) * 4;
            float4 v = *(const float4*)&W1[(k0 + kk) * 128 + c];
            ws[kk][c] = v.x; ws[kk][c + 1] = v.y; ws[kk][c + 2] = v.z; ws[kk][c + 3] = v.w;
        }
        __syncthreads();

        #pragma unroll
        for (int ks = 0; ks < 4; ks++) {
            int k = ks * 8;
            unsigned a[4][4], b[4][2];
            int ar = lane >> 2;
            int ac = k + (lane & 3);
            #pragma unroll
            for (int mf = 0; mf < 4; mf++) {
                int r = wm * 64 + mf * 16 + ar;
                a[mf][0] = f2tf(xs[r][ac]);
                a[mf][1] = f2tf(xs[r + 8][ac]);
                a[mf][2] = f2tf(xs[r][ac + 4]);
                a[mf][3] = f2tf(xs[r + 8][ac + 4]);
            }
            int bc = wn * 32 + (lane >> 2);
            int br = k + (lane & 3);
            #pragma unroll
            for (int nf = 0; nf < 4; nf++) {
                b[nf][0] = f2tf(ws[br][bc + nf * 8]);
                b[nf][1] = f2tf(ws[br + 4][bc + nf * 8]);
            }
            #pragma unroll
            for (int mf = 0; mf < 4; mf++)
                #pragma unroll
                for (int nf = 0; nf < 4; nf++)
                    mma_tf32(acc[mf][nf], a[mf], b[nf]);
        }
    }

    // epilogue: scale by dinv, store to d_g1
    #pragma unroll
    for (int mf = 0; mf < 4; mf++) {
        int r0 = row0 + wm * 64 + mf * 16 + (lane >> 2);
        int r1 = r0 + 8;
        float s0 = (r0 < n) ? d_dinv[r0] : 0.f;
        float s1 = (r1 < n) ? d_dinv[r1] : 0.f;
        #pragma unroll
        for (int nf = 0; nf < 4; nf++) {
            int c = wn * 32 + nf * 8 + (lane & 3) * 2;
            if (r0 < n) {
                float2 o = make_float2(acc[mf][nf][0] * s0, acc[mf][nf][1] * s0);
                *(float2*)&d_g1[r0 * 128 + c] = o;
            }
            if (r1 < n) {
                float2 o = make_float2(acc[mf][nf][2] * s1, acc[mf][nf][3] * s1);
                *(float2*)&d_g1[r1 * 128 + c] = o;
            }
        }
    }
}

// ---------------- Layer 1 aggregation: one warp per node ----------------

__global__ __launch_bounds__(256) void k_agg1(const float* __restrict__ b1, int n) {
    int w = (blockIdx.x * 256 + threadIdx.x) >> 5;
    int lane = threadIdx.x & 31;
    if (w >= n) return;
    const float4* g1 = (const float4*)d_g1;
    float4 acc = g1[w * 32 + lane];
    int e = d_rowptr[w], end = d_rowptr[w + 1];
    for (; e + 4 <= end; e += 4) {
        int s0 = d_col[e], s1 = d_col[e + 1], s2 = d_col[e + 2], s3 = d_col[e + 3];
        float4 v0 = g1[s0 * 32 + lane];
        float4 v1 = g1[s1 * 32 + lane];
        float4 v2 = g1[s2 * 32 + lane];
        float4 v3 = g1[s3 * 32 + lane];
        acc.x += (v0.x + v1.x) + (v2.x + v3.x);
        acc.y += (v0.y + v1.y) + (v2.y + v3.y);
        acc.z += (v0.z + v1.z) + (v2.z + v3.z);
        acc.w += (v0.w + v1.w) + (v2.w + v3.w);
    }
    for (; e < end; e++) {
        int s = d_col[e];
        float4 v = g1[s * 32 + lane];
        acc.x += v.x; acc.y += v.y; acc.z += v.z; acc.w += v.w;
    }
    float sc = d_dinv[w];
    float4 bb = ((const float4*)b1)[lane];
    float4 o;
    o.x = fmaxf(fmaf(sc, acc.x, bb.x), 0.f);
    o.y = fmaxf(fmaf(sc, acc.y, bb.y), 0.f);
    o.z = fmaxf(fmaf(sc, acc.z, bb.z), 0.f);
    o.w = fmaxf(fmaf(sc, acc.w, bb.w), 0.f);
    ((float4*)d_out1)[w * 32 + lane] = o;
}

// ---------------- Layer 2 GEMM: g2 = (out1 @ W2) * dinv ----------------

__global__ __launch_bounds__(256) void k_gemm2(const float* __restrict__ W2, int n) {
    int t = blockIdx.x * blockDim.x + threadIdx.x;
    int row = t >> 2;
    int part = t & 3;
    if (row >= n) return;
    const float4* h = (const float4*)(d_out1 + row * 128);
    const float4* w = (const float4*)W2;
    float4 acc = make_float4(0.f, 0.f, 0.f, 0.f);
    #pragma unroll
    for (int k4 = 0; k4 < 32; k4++) {
        float4 a = h[k4];
        float4 w0 = w[(k4 * 4 + 0) * 4 + part];
        float4 w1 = w[(k4 * 4 + 1) * 4 + part];
        float4 w2v = w[(k4 * 4 + 2) * 4 + part];
        float4 w3 = w[(k4 * 4 + 3) * 4 + part];
        acc.x += a.x * w0.x + a.y * w1.x + a.z * w2v.x + a.w * w3.x;
        acc.y += a.x * w0.y + a.y * w1.y + a.z * w2v.y + a.w * w3.y;
        acc.z += a.x * w0.z + a.y * w1.z + a.z * w2v.z + a.w * w3.z;
        acc.w += a.x * w0.w + a.y * w1.w + a.z * w2v.w + a.w * w3.w;
    }
    float sc = d_dinv[row];
    ((float4*)d_g2)[row * 4 + part] =
        make_float4(acc.x * sc, acc.y * sc, acc.z * sc, acc.w * sc);
}

// ---------------- Layer 2 aggregation + final output ----------------

__global__ __launch_bounds__(256) void k_agg2(const float* __restrict__ b2,
                                              float* __restrict__ out, int n) {
    int t = blockIdx.x * blockDim.x + threadIdx.x;
    int row = t >> 2;
    int part = t & 3;
    if (row >= n) return;
    const float4* g2 = (const float4*)d_g2;
    float4 acc = g2[row * 4 + part];
    int e = d_rowptr[row], end = d_rowptr[row + 1];
    for (; e + 4 <= end; e += 4) {
        int s0 = d_col[e], s1 = d_col[e + 1], s2 = d_col[e + 2], s3 = d_col[e + 3];
        float4 v0 = g2[s0 * 4 + part];
        float4 v1 = g2[s1 * 4 + part];
        float4 v2 = g2[s2 * 4 + part];
        float4 v3 = g2[s3 * 4 + part];
        acc.x += (v0.x + v1.x) + (v2.x + v3.x);
        acc.y += (v0.y + v1.y) + (v2.y + v3.y);
        acc.z += (v0.z + v1.z) + (v2.z + v3.z);
        acc.w += (v0.w + v1.w) + (v2.w + v3.w);
    }
    for (; e < end; e++) {
        int s = d_col[e];
        float4 v = g2[s * 4 + part];
        acc.x += v.x; acc.y += v.y; acc.z += v.z; acc.w += v.w;
    }
    float sc = d_dinv[row];
    float4 bb = ((const float4*)b2)[part];
    float4 o;
    o.x = fmaf(sc, acc.x, bb.x);
    o.y = fmaf(sc, acc.y, bb.y);
    o.z = fmaf(sc, acc.z, bb.z);
    o.w = fmaf(sc, acc.w, bb.w);
    *(float4*)&out[row * 16 + part * 4] = o;
}

// ---------------- launch ----------------

extern "C" void kernel_launch(void* const* d_in, const int* in_sizes, int n_in,
                              void* d_out, int out_size) {
    const float* x  = (const float*)d_in[0];
    const void*  ei = d_in[1];
    const float* W1 = (const float*)d_in[2];
    const float* b1 = (const float*)d_in[3];
    const float* W2 = (const float*)d_in[4];
    const float* b2 = (const float*)d_in[5];
    float* out = (float*)d_out;

    int n = in_sizes[0] / 256;
    int e = in_sizes[1] / 2;
    int nb_scan = (n + 1023) / 1024;

    k_detect<<<1, 32>>>((const unsigned*)ei);
    k_zero <<<(n + 255) / 256, 256>>>(n);
    k_deg  <<<(e + 255) / 256, 256>>>(ei, e, n);
    k_scan1<<<nb_scan, 1024>>>(n);
    k_scan2<<<1, 128>>>(nb_scan);
    k_scan3<<<nb_scan, 1024>>>(n, e);
    k_fill <<<(e + 255) / 256, 256>>>(ei, e, n);

    k_gemm1_tc<<<(n + 127) / 128, 256>>>(x, W1, n);
    k_agg1 <<<(n * 32 + 255) / 256, 256>>>(b1, n);
    k_gemm2<<<(n * 4 + 255) / 256, 256>>>(W2, n);
    k_agg2 <<<(n * 4 + 255) / 256, 256>>>(b2, out, n);
}

// round 7
// speedup vs baseline: 1.7970x; 1.0877x over previous
#include <cuda_runtime.h>
#include <cuda_fp16.h>

// ---------------------------------------------------------------------------
// 2-layer GCN, pull-based aggregation over per-call CSR-by-dst.
//   g = (h @ W) * dinv[row];  agg[d] = dinv[d]*(sum_in g[src] + g[d])
// GEMM1 on tf32 tensor cores. Gathered messages g1/g2 stored fp16
// (fp32 accumulate) to halve the L2 gather roofline.
// edge_index dtype probed at runtime (int32 vs int64).
// ---------------------------------------------------------------------------

#define MAXN 100000
#define MAXE 1600000

__device__ int    d_mode;
__device__ int    d_counts[MAXN];
__device__ int    d_cursor[MAXN];
__device__ int    d_rowptr[MAXN + 1];
__device__ int    d_col[MAXE];
__device__ float  d_dinv[MAXN];
__device__ __half d_g1[MAXN * 128];    // (x@W1)*dinv, fp16
__device__ float  d_out1[MAXN * 128];  // relu(layer1), fp32
__device__ __half d_g2[MAXN * 16];     // (out1@W2)*dinv, fp16
__device__ int    d_bsums[128];

// ---------------- zero + dtype probe (fused) ----------------

__global__ void k_zero(const unsigned* __restrict__ ei_w, int n) {
    int i = blockIdx.x * blockDim.x + threadIdx.x;
    if (i < n) { d_counts[i] = 0; d_cursor[i] = 0; }
    if (blockIdx.x == 0 && threadIdx.x < 32) {
        int l = threadIdx.x;
        unsigned any = 0;
        #pragma unroll
        for (int j = 0; j < 8; j++) any |= ei_w[2 * (l + j * 32) + 1];
        unsigned ball = __ballot_sync(0xFFFFFFFFu, any != 0);
        if (l == 0) d_mode = (ball == 0) ? 1 : 0;
    }
}

__device__ __forceinline__ int load_idx(const void* ei, int e, int which, int i) {
    if (d_mode) return (int)((const long long*)ei)[(long long)which * e + i];
    return ((const int*)ei)[which * e + i];
}

// ---------------- CSR build ----------------

__global__ void k_deg(const void* __restrict__ ei, int e, int n) {
    int i = blockIdx.x * blockDim.x + threadIdx.x;
    if (i < e) {
        int d = load_idx(ei, e, 1, i);
        if ((unsigned)d < (unsigned)n) atomicAdd(&d_counts[d], 1);
    }
}

__global__ void k_scan1(int n) {
    __shared__ int s[1024];
    int t = threadIdx.x;
    int i = blockIdx.x * 1024 + t;
    int v = (i < n) ? d_counts[i] : 0;
    if (i < n) d_dinv[i] = rsqrtf((float)(v + 1));
    s[t] = v;
    __syncthreads();
    for (int off = 1; off < 1024; off <<= 1) {
        int a = (t >= off) ? s[t - off] : 0;
        __syncthreads();
        s[t] += a;
        __syncthreads();
    }
    if (i < n) d_rowptr[i] = s[t] - v;
    if (t == 1023) d_bsums[blockIdx.x] = s[t];
}

__global__ void k_scan2(int nb) {
    __shared__ int s[128];
    int t = threadIdx.x;
    int v = (t < nb) ? d_bsums[t] : 0;
    s[t] = v;
    __syncthreads();
    for (int off = 1; off < 128; off <<= 1) {
        int a = (t >= off) ? s[t - off] : 0;
        __syncthreads();
        s[t] += a;
        __syncthreads();
    }
    if (t < nb) d_bsums[t] = s[t] - v;
}

__global__ void k_scan3(int n, int e) {
    int i = blockIdx.x * 1024 + threadIdx.x;
    if (i < n) d_rowptr[i] += d_bsums[blockIdx.x];
    if (i == 0) d_rowptr[n] = e;
}

__global__ void k_fill(const void* __restrict__ ei, int e, int n) {
    int i = blockIdx.x * blockDim.x + threadIdx.x;
    if (i < e) {
        int s = load_idx(ei, e, 0, i);
        int d = load_idx(ei, e, 1, i);
        if ((unsigned)d < (unsigned)n && (unsigned)s < (unsigned)n) {
            int pos = d_rowptr[d] + atomicAdd(&d_cursor[d], 1);
            d_col[pos] = s;
        }
    }
}

// ---------------- Layer 1 GEMM (tf32 tensor cores) ----------------

__device__ __forceinline__ unsigned f2tf(float f) {
    unsigned u;
    asm("cvt.rna.tf32.f32 %0, %1;" : "=r"(u) : "f"(f));
    return u;
}

__device__ __forceinline__ void mma_tf32(float* d, const unsigned* a, const unsigned* b) {
    asm volatile(
        "mma.sync.aligned.m16n8k8.row.col.f32.tf32.tf32.f32 "
        "{%0,%1,%2,%3}, {%4,%5,%6,%7}, {%8,%9}, {%0,%1,%2,%3};"
        : "+f"(d[0]), "+f"(d[1]), "+f"(d[2]), "+f"(d[3])
        : "r"(a[0]), "r"(a[1]), "r"(a[2]), "r"(a[3]), "r"(b[0]), "r"(b[1]));
}

__global__ __launch_bounds__(256) void k_gemm1_tc(const float* __restrict__ x,
                                                  const float* __restrict__ W1,
                                                  int n) {
    __shared__ float xs[128][36];
    __shared__ float ws[32][136];
    int tid = threadIdx.x;
    int lane = tid & 31;
    int wid = tid >> 5;
    int wm = wid & 1;
    int wn = wid >> 1;
    int row0 = blockIdx.x * 128;

    float acc[4][4][4];
    #pragma unroll
    for (int i = 0; i < 4; i++)
        #pragma unroll
        for (int j = 0; j < 4; j++)
            #pragma unroll
            for (int r = 0; r < 4; r++) acc[i][j][r] = 0.f;

    for (int k0 = 0; k0 < 256; k0 += 32) {
        if (k0) __syncthreads();
        #pragma unroll
        for (int i = 0; i < 4; i++) {
            int f = tid + i * 256;
            int r = f >> 3;
            int c = (f & 7) * 4;
            float4 v = make_float4(0.f, 0.f, 0.f, 0.f);
            if (row0 + r < n) v = *(const float4*)&x[(row0 + r) * 256 + k0 + c];
            xs[r][c] = v.x; xs[r][c + 1] = v.y; xs[r][c + 2] = v.z; xs[r][c + 3] = v.w;
        }
        #pragma unroll
        for (int i = 0; i < 4; i++) {
            int f = tid + i * 256;
            int kk = f >> 5;
            int c = (f & 31) * 4;
            float4 v = *(const float4*)&W1[(k0 + kk) * 128 + c];
            ws[kk][c] = v.x; ws[kk][c + 1] = v.y; ws[kk][c + 2] = v.z; ws[kk][c + 3] = v.w;
        }
        __syncthreads();

        #pragma unroll
        for (int ks = 0; ks < 4; ks++) {
            int k = ks * 8;
            unsigned a[4][4], b[4][2];
            int ar = lane >> 2;
            int ac = k + (lane & 3);
            #pragma unroll
            for (int mf = 0; mf < 4; mf++) {
                int r = wm * 64 + mf * 16 + ar;
                a[mf][0] = f2tf(xs[r][ac]);
                a[mf][1] = f2tf(xs[r + 8][ac]);
                a[mf][2] = f2tf(xs[r][ac + 4]);
                a[mf][3] = f2tf(xs[r + 8][ac + 4]);
            }
            int bc = wn * 32 + (lane >> 2);
            int br = k + (lane & 3);
            #pragma unroll
            for (int nf = 0; nf < 4; nf++) {
                b[nf][0] = f2tf(ws[br][bc + nf * 8]);
                b[nf][1] = f2tf(ws[br + 4][bc + nf * 8]);
            }
            #pragma unroll
            for (int mf = 0; mf < 4; mf++)
                #pragma unroll
                for (int nf = 0; nf < 4; nf++)
                    mma_tf32(acc[mf][nf], a[mf], b[nf]);
        }
    }

    // epilogue: scale by dinv, store fp16 to d_g1
    #pragma unroll
    for (int mf = 0; mf < 4; mf++) {
        int r0 = row0 + wm * 64 + mf * 16 + (lane >> 2);
        int r1 = r0 + 8;
        float s0 = (r0 < n) ? d_dinv[r0] : 0.f;
        float s1 = (r1 < n) ? d_dinv[r1] : 0.f;
        #pragma unroll
        for (int nf = 0; nf < 4; nf++) {
            int c = wn * 32 + nf * 8 + (lane & 3) * 2;
            if (r0 < n)
                *(__half2*)&d_g1[r0 * 128 + c] =
                    __floats2half2_rn(acc[mf][nf][0] * s0, acc[mf][nf][1] * s0);
            if (r1 < n)
                *(__half2*)&d_g1[r1 * 128 + c] =
                    __floats2half2_rn(acc[mf][nf][2] * s1, acc[mf][nf][3] * s1);
        }
    }
}

// ---------------- fp16 gather helpers ----------------

__device__ __forceinline__ float4 ld_g1h(int row, int lane) {
    uint2 u = *(const uint2*)(d_g1 + row * 128 + lane * 4);
    float2 f0 = __half22float2(*(__half2*)&u.x);
    float2 f1 = __half22float2(*(__half2*)&u.y);
    return make_float4(f0.x, f0.y, f1.x, f1.y);
}

__device__ __forceinline__ float4 ld_g2h(int row, int part) {
    uint2 u = *(const uint2*)(d_g2 + row * 16 + part * 4);
    float2 f0 = __half22float2(*(__half2*)&u.x);
    float2 f1 = __half22float2(*(__half2*)&u.y);
    return make_float4(f0.x, f0.y, f1.x, f1.y);
}

// ---------------- Layer 1 aggregation: one warp per node ----------------

__global__ __launch_bounds__(256) void k_agg1(const float* __restrict__ b1, int n) {
    int w = (blockIdx.x * 256 + threadIdx.x) >> 5;
    int lane = threadIdx.x & 31;
    if (w >= n) return;
    float4 acc = ld_g1h(w, lane);      // self-loop
    int e = d_rowptr[w], end = d_rowptr[w + 1];
    for (; e + 4 <= end; e += 4) {
        int s0 = d_col[e], s1 = d_col[e + 1], s2 = d_col[e + 2], s3 = d_col[e + 3];
        float4 v0 = ld_g1h(s0, lane);
        float4 v1 = ld_g1h(s1, lane);
        float4 v2 = ld_g1h(s2, lane);
        float4 v3 = ld_g1h(s3, lane);
        acc.x += (v0.x + v1.x) + (v2.x + v3.x);
        acc.y += (v0.y + v1.y) + (v2.y + v3.y);
        acc.z += (v0.z + v1.z) + (v2.z + v3.z);
        acc.w += (v0.w + v1.w) + (v2.w + v3.w);
    }
    for (; e < end; e++) {
        float4 v = ld_g1h(d_col[e], lane);
        acc.x += v.x; acc.y += v.y; acc.z += v.z; acc.w += v.w;
    }
    float sc = d_dinv[w];
    float4 bb = ((const float4*)b1)[lane];
    float4 o;
    o.x = fmaxf(fmaf(sc, acc.x, bb.x), 0.f);
    o.y = fmaxf(fmaf(sc, acc.y, bb.y), 0.f);
    o.z = fmaxf(fmaf(sc, acc.z, bb.z), 0.f);
    o.w = fmaxf(fmaf(sc, acc.w, bb.w), 0.f);
    ((float4*)d_out1)[w * 32 + lane] = o;
}

// ---------------- Layer 2 GEMM: g2 = (out1 @ W2) * dinv, fp16 out ----------

__global__ __launch_bounds__(256) void k_gemm2(const float* __restrict__ W2, int n) {
    int t = blockIdx.x * blockDim.x + threadIdx.x;
    int row = t >> 2;
    int part = t & 3;
    if (row >= n) return;
    const float4* h = (const float4*)(d_out1 + row * 128);
    const float4* w = (const float4*)W2;
    float4 acc = make_float4(0.f, 0.f, 0.f, 0.f);
    #pragma unroll
    for (int k4 = 0; k4 < 32; k4++) {
        float4 a = h[k4];
        float4 w0 = w[(k4 * 4 + 0) * 4 + part];
        float4 w1 = w[(k4 * 4 + 1) * 4 + part];
        float4 w2v = w[(k4 * 4 + 2) * 4 + part];
        float4 w3 = w[(k4 * 4 + 3) * 4 + part];
        acc.x += a.x * w0.x + a.y * w1.x + a.z * w2v.x + a.w * w3.x;
        acc.y += a.x * w0.y + a.y * w1.y + a.z * w2v.y + a.w * w3.y;
        acc.z += a.x * w0.z + a.y * w1.z + a.z * w2v.z + a.w * w3.z;
        acc.w += a.x * w0.w + a.y * w1.w + a.z * w2v.w + a.w * w3.w;
    }
    float sc = d_dinv[row];
    __half2 p0 = __floats2half2_rn(acc.x * sc, acc.y * sc);
    __half2 p1 = __floats2half2_rn(acc.z * sc, acc.w * sc);
    uint2 u;
    u.x = *(unsigned*)&p0;
    u.y = *(unsigned*)&p1;
    *(uint2*)(d_g2 + row * 16 + part * 4) = u;
}

// ---------------- Layer 2 aggregation + final output ----------------

__global__ __launch_bounds__(256) void k_agg2(const float* __restrict__ b2,
                                              float* __restrict__ out, int n) {
    int t = blockIdx.x * blockDim.x + threadIdx.x;
    int row = t >> 2;
    int part = t & 3;
    if (row >= n) return;
    float4 acc = ld_g2h(row, part);    // self-loop
    int e = d_rowptr[row], end = d_rowptr[row + 1];
    for (; e + 4 <= end; e += 4) {
        int s0 = d_col[e], s1 = d_col[e + 1], s2 = d_col[e + 2], s3 = d_col[e + 3];
        float4 v0 = ld_g2h(s0, part);
        float4 v1 = ld_g2h(s1, part);
        float4 v2 = ld_g2h(s2, part);
        float4 v3 = ld_g2h(s3, part);
        acc.x += (v0.x + v1.x) + (v2.x + v3.x);
        acc.y += (v0.y + v1.y) + (v2.y + v3.y);
        acc.z += (v0.z + v1.z) + (v2.z + v3.z);
        acc.w += (v0.w + v1.w) + (v2.w + v3.w);
    }
    for (; e < end; e++) {
        float4 v = ld_g2h(d_col[e], part);
        acc.x += v.x; acc.y += v.y; acc.z += v.z; acc.w += v.w;
    }
    float sc = d_dinv[row];
    float4 bb = ((const float4*)b2)[part];
    float4 o;
    o.x = fmaf(sc, acc.x, bb.x);
    o.y = fmaf(sc, acc.y, bb.y);
    o.z = fmaf(sc, acc.z, bb.z);
    o.w = fmaf(sc, acc.w, bb.w);
    *(float4*)&out[row * 16 + part * 4] = o;
}

// ---------------- launch ----------------

extern "C" void kernel_launch(void* const* d_in, const int* in_sizes, int n_in,
                              void* d_out, int out_size) {
    const float* x  = (const float*)d_in[0];
    const void*  ei = d_in[1];
    const float* W1 = (const float*)d_in[2];
    const float* b1 = (const float*)d_in[3];
    const float* W2 = (const float*)d_in[4];
    const float* b2 = (const float*)d_in[5];
    float* out = (float*)d_out;

    int n = in_sizes[0] / 256;
    int e = in_sizes[1] / 2;
    int nb_scan = (n + 1023) / 1024;

    k_zero <<<(n + 255) / 256, 256>>>((const unsigned*)ei, n);
    k_deg  <<<(e + 255) / 256, 256>>>(ei, e, n);
    k_scan1<<<nb_scan, 1024>>>(n);
    k_scan2<<<1, 128>>>(nb_scan);
    k_scan3<<<nb_scan, 1024>>>(n, e);
    k_fill <<<(e + 255) / 256, 256>>>(ei, e, n);

    k_gemm1_tc<<<(n + 127) / 128, 256>>>(x, W1, n);
    k_agg1 <<<(n * 32 + 255) / 256, 256>>>(b1, n);
    k_gemm2<<<(n * 4 + 255) / 256, 256>>>(W2, n);
    k_agg2 <<<(n * 4 + 255) / 256, 256>>>(b2, out, n);
}

// round 10
// speedup vs baseline: 1.8830x; 1.0478x over previous
#include <cuda_runtime.h>
#include <cuda_fp16.h>

// ---------------------------------------------------------------------------
// 2-layer GCN, pull-based aggregation over per-call CSR-by-dst.
//   g = (h @ W) * dinv[row];  agg[d] = dinv[d]*(sum_in g[src] + g[d])
// GEMM1 on tf32 tensor cores. Messages g1/g2 and hidden out1 stored fp16
// (fp32 accumulate). agg1: half-warp per node for 2x gather MLP.
// edge_index dtype probed at runtime (int32 vs int64).
// ---------------------------------------------------------------------------

#define MAXN 100000
#define MAXE 1600000

__device__ int    d_mode;
__device__ int    d_counts[MAXN];
__device__ int    d_cursor[MAXN];
__device__ int    d_rowptr[MAXN + 1];
__device__ int    d_col[MAXE];
__device__ float  d_dinv[MAXN];
__device__ __half d_g1[MAXN * 128];    // (x@W1)*dinv, fp16
__device__ __half d_out1[MAXN * 128];  // relu(layer1), fp16
__device__ __half d_g2[MAXN * 16];     // (out1@W2)*dinv, fp16
__device__ int    d_bsums[128];

// ---------------- zero + dtype probe (fused) ----------------

__global__ void k_zero(const unsigned* __restrict__ ei_w, int n) {
    int i = blockIdx.x * blockDim.x + threadIdx.x;
    if (i < n) { d_counts[i] = 0; d_cursor[i] = 0; }
    if (blockIdx.x == 0 && threadIdx.x < 32) {
        int l = threadIdx.x;
        unsigned any = 0;
        #pragma unroll
        for (int j = 0; j < 8; j++) any |= ei_w[2 * (l + j * 32) + 1];
        unsigned ball = __ballot_sync(0xFFFFFFFFu, any != 0);
        if (l == 0) d_mode = (ball == 0) ? 1 : 0;
    }
}

__device__ __forceinline__ int load_idx(const void* ei, int e, int which, int i) {
    if (d_mode) return (int)((const long long*)ei)[(long long)which * e + i];
    return ((const int*)ei)[which * e + i];
}

// ---------------- CSR build ----------------

__global__ void k_deg(const void* __restrict__ ei, int e, int n) {
    int i = blockIdx.x * blockDim.x + threadIdx.x;
    if (i < e) {
        int d = load_idx(ei, e, 1, i);
        if ((unsigned)d < (unsigned)n) atomicAdd(&d_counts[d], 1);
    }
}

__global__ void k_scan1(int n) {
    __shared__ int s[1024];
    int t = threadIdx.x;
    int i = blockIdx.x * 1024 + t;
    int v = (i < n) ? d_counts[i] : 0;
    if (i < n) d_dinv[i] = rsqrtf((float)(v + 1));
    s[t] = v;
    __syncthreads();
    for (int off = 1; off < 1024; off <<= 1) {
        int a = (t >= off) ? s[t - off] : 0;
        __syncthreads();
        s[t] += a;
        __syncthreads();
    }
    if (i < n) d_rowptr[i] = s[t] - v;
    if (t == 1023) d_bsums[blockIdx.x] = s[t];
}

__global__ void k_scan2(int nb) {
    __shared__ int s[128];
    int t = threadIdx.x;
    int v = (t < nb) ? d_bsums[t] : 0;
    s[t] = v;
    __syncthreads();
    for (int off = 1; off < 128; off <<= 1) {
        int a = (t >= off) ? s[t - off] : 0;
        __syncthreads();
        s[t] += a;
        __syncthreads();
    }
    if (t < nb) d_bsums[t] = s[t] - v;
}

__global__ void k_scan3(int n, int e) {
    int i = blockIdx.x * 1024 + threadIdx.x;
    if (i < n) d_rowptr[i] += d_bsums[blockIdx.x];
    if (i == 0) d_rowptr[n] = e;
}

__global__ void k_fill(const void* __restrict__ ei, int e, int n) {
    int i = blockIdx.x * blockDim.x + threadIdx.x;
    if (i < e) {
        int s = load_idx(ei, e, 0, i);
        int d = load_idx(ei, e, 1, i);
        if ((unsigned)d < (unsigned)n && (unsigned)s < (unsigned)n) {
            int pos = d_rowptr[d] + atomicAdd(&d_cursor[d], 1);
            d_col[pos] = s;
        }
    }
}

// ---------------- Layer 1 GEMM (tf32 tensor cores) ----------------

__device__ __forceinline__ unsigned f2tf(float f) {
    unsigned u;
    asm("cvt.rna.tf32.f32 %0, %1;" : "=r"(u) : "f"(f));
    return u;
}

__device__ __forceinline__ void mma_tf32(float* d, const unsigned* a, const unsigned* b) {
    asm volatile(
        "mma.sync.aligned.m16n8k8.row.col.f32.tf32.tf32.f32 "
        "{%0,%1,%2,%3}, {%4,%5,%6,%7}, {%8,%9}, {%0,%1,%2,%3};"
        : "+f"(d[0]), "+f"(d[1]), "+f"(d[2]), "+f"(d[3])
        : "r"(a[0]), "r"(a[1]), "r"(a[2]), "r"(a[3]), "r"(b[0]), "r"(b[1]));
}

__global__ __launch_bounds__(256) void k_gemm1_tc(const float* __restrict__ x,
                                                  const float* __restrict__ W1,
                                                  int n) {
    __shared__ float xs[128][36];
    __shared__ float ws[32][136];
    int tid = threadIdx.x;
    int lane = tid & 31;
    int wid = tid >> 5;
    int wm = wid & 1;
    int wn = wid >> 1;
    int row0 = blockIdx.x * 128;

    float acc[4][4][4];
    #pragma unroll
    for (int i = 0; i < 4; i++)
        #pragma unroll
        for (int j = 0; j < 4; j++)
            #pragma unroll
            for (int r = 0; r < 4; r++) acc[i][j][r] = 0.f;

    for (int k0 = 0; k0 < 256; k0 += 32) {
        if (k0) __syncthreads();
        #pragma unroll
        for (int i = 0; i < 4; i++) {
            int f = tid + i * 256;
            int r = f >> 3;
            int c = (f & 7) * 4;
            float4 v = make_float4(0.f, 0.f, 0.f, 0.f);
            if (row0 + r < n) v = *(const float4*)&x[(row0 + r) * 256 + k0 + c];
            xs[r][c] = v.x; xs[r][c + 1] = v.y; xs[r][c + 2] = v.z; xs[r][c + 3] = v.w;
        }
        #pragma unroll
        for (int i = 0; i < 4; i++) {
            int f = tid + i * 256;
            int kk = f >> 5;
            int c = (f & 31) * 4;
            float4 v = *(const float4*)&W1[(k0 + kk) * 128 + c];
            ws[kk][c] = v.x; ws[kk][c + 1] = v.y; ws[kk][c + 2] = v.z; ws[kk][c + 3] = v.w;
        }
        __syncthreads();

        #pragma unroll
        for (int ks = 0; ks < 4; ks++) {
            int k = ks * 8;
            unsigned a[4][4], b[4][2];
            int ar = lane >> 2;
            int ac = k + (lane & 3);
            #pragma unroll
            for (int mf = 0; mf < 4; mf++) {
                int r = wm * 64 + mf * 16 + ar;
                a[mf][0] = f2tf(xs[r][ac]);
                a[mf][1] = f2tf(xs[r + 8][ac]);
                a[mf][2] = f2tf(xs[r][ac + 4]);
                a[mf][3] = f2tf(xs[r + 8][ac + 4]);
            }
            int bc = wn * 32 + (lane >> 2);
            int br = k + (lane & 3);
            #pragma unroll
            for (int nf = 0; nf < 4; nf++) {
                b[nf][0] = f2tf(ws[br][bc + nf * 8]);
                b[nf][1] = f2tf(ws[br + 4][bc + nf * 8]);
            }
            #pragma unroll
            for (int mf = 0; mf < 4; mf++)
                #pragma unroll
                for (int nf = 0; nf < 4; nf++)
                    mma_tf32(acc[mf][nf], a[mf], b[nf]);
        }
    }

    #pragma unroll
    for (int mf = 0; mf < 4; mf++) {
        int r0 = row0 + wm * 64 + mf * 16 + (lane >> 2);
        int r1 = r0 + 8;
        float s0 = (r0 < n) ? d_dinv[r0] : 0.f;
        float s1 = (r1 < n) ? d_dinv[r1] : 0.f;
        #pragma unroll
        for (int nf = 0; nf < 4; nf++) {
            int c = wn * 32 + nf * 8 + (lane & 3) * 2;
            if (r0 < n)
                *(__half2*)&d_g1[r0 * 128 + c] =
                    __floats2half2_rn(acc[mf][nf][0] * s0, acc[mf][nf][1] * s0);
            if (r1 < n)
                *(__half2*)&d_g1[r1 * 128 + c] =
                    __floats2half2_rn(acc[mf][nf][2] * s1, acc[mf][nf][3] * s1);
        }
    }
}

// ---------------- fp16 helpers ----------------

__device__ __forceinline__ void acc_u4(float* acc, uint4 u) {
    float2 f0 = __half22float2(*(__half2*)&u.x);
    float2 f1 = __half22float2(*(__half2*)&u.y);
    float2 f2 = __half22float2(*(__half2*)&u.z);
    float2 f3 = __half22float2(*(__half2*)&u.w);
    acc[0] += f0.x; acc[1] += f0.y; acc[2] += f1.x; acc[3] += f1.y;
    acc[4] += f2.x; acc[5] += f2.y; acc[6] += f3.x; acc[7] += f3.y;
}

__device__ __forceinline__ float4 ld_g2h(int row, int part) {
    uint2 u = *(const uint2*)(d_g2 + row * 16 + part * 4);
    float2 f0 = __half22float2(*(__half2*)&u.x);
    float2 f1 = __half22float2(*(__half2*)&u.y);
    return make_float4(f0.x, f0.y, f1.x, f1.y);
}

// ---------------- Layer 1 aggregation: half-warp per node ----------------
// 16 lanes per node, 8 features (16B) per lane. 2 nodes per warp -> 2x MLP.

__global__ __launch_bounds__(256) void k_agg1(const float* __restrict__ b1, int n) {
    int gw = (blockIdx.x * 256 + threadIdx.x) >> 4;   // node index
    int sl = threadIdx.x & 15;                         // sub-lane 0..15
    if (gw >= n) return;
    const __half* g1 = d_g1;
    int fo = sl * 8;                                   // feature offset

    float acc[8] = {};
    acc_u4(acc, *(const uint4*)(g1 + gw * 128 + fo));  // self-loop

    int e = d_rowptr[gw], end = d_rowptr[gw + 1];
    for (; e + 4 <= end; e += 4) {
        int s0 = d_col[e], s1 = d_col[e + 1], s2 = d_col[e + 2], s3 = d_col[e + 3];
        uint4 u0 = *(const uint4*)(g1 + s0 * 128 + fo);
        uint4 u1 = *(const uint4*)(g1 + s1 * 128 + fo);
        uint4 u2 = *(const uint4*)(g1 + s2 * 128 + fo);
        uint4 u3 = *(const uint4*)(g1 + s3 * 128 + fo);
        acc_u4(acc, u0); acc_u4(acc, u1); acc_u4(acc, u2); acc_u4(acc, u3);
    }
    for (; e < end; e++)
        acc_u4(acc, *(const uint4*)(g1 + d_col[e] * 128 + fo));

    float sc = d_dinv[gw];
    float4 bb0 = ((const float4*)b1)[sl * 2];
    float4 bb1 = ((const float4*)b1)[sl * 2 + 1];
    float o0 = fmaxf(fmaf(sc, acc[0], bb0.x), 0.f);
    float o1 = fmaxf(fmaf(sc, acc[1], bb0.y), 0.f);
    float o2 = fmaxf(fmaf(sc, acc[2], bb0.z), 0.f);
    float o3 = fmaxf(fmaf(sc, acc[3], bb0.w), 0.f);
    float o4 = fmaxf(fmaf(sc, acc[4], bb1.x), 0.f);
    float o5 = fmaxf(fmaf(sc, acc[5], bb1.y), 0.f);
    float o6 = fmaxf(fmaf(sc, acc[6], bb1.z), 0.f);
    float o7 = fmaxf(fmaf(sc, acc[7], bb1.w), 0.f);
    __half2 p0 = __floats2half2_rn(o0, o1);
    __half2 p1 = __floats2half2_rn(o2, o3);
    __half2 p2 = __floats2half2_rn(o4, o5);
    __half2 p3 = __floats2half2_rn(o6, o7);
    uint4 u;
    u.x = *(unsigned*)&p0; u.y = *(unsigned*)&p1;
    u.z = *(unsigned*)&p2; u.w = *(unsigned*)&p3;
    *(uint4*)(d_out1 + gw * 128 + fo) = u;
}

// ---------------- Layer 2 GEMM: g2 = (out1 @ W2) * dinv, fp16 in/out ------

__global__ __launch_bounds__(256) void k_gemm2(const float* __restrict__ W2, int n) {
    int t = blockIdx.x * blockDim.x + threadIdx.x;
    int row = t >> 2;
    int part = t & 3;
    if (row >= n) return;
    const uint4* h = (const uint4*)(d_out1 + row * 128);   // 16 x uint4 (8 halves)
    const float4* w = (const float4*)W2;                   // W2[128][16]
    float4 acc = make_float4(0.f, 0.f, 0.f, 0.f);
    #pragma unroll
    for (int k8 = 0; k8 < 16; k8++) {
        uint4 u = h[k8];
        float2 f0 = __half22float2(*(__half2*)&u.x);
        float2 f1 = __half22float2(*(__half2*)&u.y);
        float2 f2 = __half22float2(*(__half2*)&u.z);
        float2 f3 = __half22float2(*(__half2*)&u.w);
        float a[8] = {f0.x, f0.y, f1.x, f1.y, f2.x, f2.y, f3.x, f3.y};
        #pragma unroll
        for (int i = 0; i < 8; i++) {
            float4 wv = w[(k8 * 8 + i) * 4 + part];
            acc.x += a[i] * wv.x;
            acc.y += a[i] * wv.y;
            acc.z += a[i] * wv.z;
            acc.w += a[i] * wv.w;
        }
    }
    float sc = d_dinv[row];
    __half2 p0 = __floats2half2_rn(acc.x * sc, acc.y * sc);
    __half2 p1 = __floats2half2_rn(acc.z * sc, acc.w * sc);
    uint2 u;
    u.x = *(unsigned*)&p0;
    u.y = *(unsigned*)&p1;
    *(uint2*)(d_g2 + row * 16 + part * 4) = u;
}

// ---------------- Layer 2 aggregation + final output ----------------

__global__ __launch_bounds__(256) void k_agg2(const float* __restrict__ b2,
                                              float* __restrict__ out, int n) {
    int t = blockIdx.x * blockDim.x + threadIdx.x;
    int row = t >> 2;
    int part = t & 3;
    if (row >= n) return;
    float4 acc = ld_g2h(row, part);    // self-loop
    int e = d_rowptr[row], end = d_rowptr[row + 1];
    for (; e + 4 <= end; e += 4) {
        int s0 = d_col[e], s1 = d_col[e + 1], s2 = d_col[e + 2], s3 = d_col[e + 3];
        float4 v0 = ld_g2h(s0, part);
        float4 v1 = ld_g2h(s1, part);
        float4 v2 = ld_g2h(s2, part);
        float4 v3 = ld_g2h(s3, part);
        acc.x += (v0.x + v1.x) + (v2.x + v3.x);
        acc.y += (v0.y + v1.y) + (v2.y + v3.y);
        acc.z += (v0.z + v1.z) + (v2.z + v3.z);
        acc.w += (v0.w + v1.w) + (v2.w + v3.w);
    }
    for (; e < end; e++) {
        float4 v = ld_g2h(d_col[e], part);
        acc.x += v.x; acc.y += v.y; acc.z += v.z; acc.w += v.w;
    }
    float sc = d_dinv[row];
    float4 bb = ((const float4*)b2)[part];
    float4 o;
    o.x = fmaf(sc, acc.x, bb.x);
    o.y = fmaf(sc, acc.y, bb.y);
    o.z = fmaf(sc, acc.z, bb.z);
    o.w = fmaf(sc, acc.w, bb.w);
    *(float4*)&out[row * 16 + part * 4] = o;
}

// ---------------- launch ----------------

extern "C" void kernel_launch(void* const* d_in, const int* in_sizes, int n_in,
                              void* d_out, int out_size) {
    const float* x  = (const float*)d_in[0];
    const void*  ei = d_in[1];
    const float* W1 = (const float*)d_in[2];
    const float* b1 = (const float*)d_in[3];
    const float* W2 = (const float*)d_in[4];
    const float* b2 = (const float*)d_in[5];
    float* out = (float*)d_out;

    int n = in_sizes[0] / 256;
    int e = in_sizes[1] / 2;
    int nb_scan = (n + 1023) / 1024;

    k_zero <<<(n + 255) / 256, 256>>>((const unsigned*)ei, n);
    k_deg  <<<(e + 255) / 256, 256>>>(ei, e, n);
    k_scan1<<<nb_scan, 1024>>>(n);
    k_scan2<<<1, 128>>>(nb_scan);
    k_scan3<<<nb_scan, 1024>>>(n, e);
    k_fill <<<(e + 255) / 256, 256>>>(ei, e, n);

    k_gemm1_tc<<<(n + 127) / 128, 256>>>(x, W1, n);
    k_agg1 <<<(n * 16 + 255) / 256, 256>>>(b1, n);
    k_gemm2<<<(n * 4 + 255) / 256, 256>>>(W2, n);
    k_agg2 <<<(n * 4 + 255) / 256, 256>>>(b2, out, n);
}

// round 11
// speedup vs baseline: 1.8887x; 1.0030x over previous
#include <cuda_runtime.h>
#include <cuda_fp16.h>

// ---------------------------------------------------------------------------
// 2-layer GCN, pull aggregation over per-call CSR-by-dst.
//   g = (h @ W) * dinv[row];  agg[d] = dinv[d]*(sum_in g[src] + g[d])
// GEMM1 on tf32 tensor cores. g1/out1/g2 fp16 (fp32 accumulate).
// CSR offsets via block-aggregated atomic bump (order-free) -- no scan chain.
// edge_index dtype probed at runtime (int32 vs int64).
// ---------------------------------------------------------------------------

#define MAXN 100000
#define MAXE 1600000

__device__ int    d_mode;
__device__ int    d_ctr;
__device__ int    d_counts[MAXN];
__device__ int    d_cursor[MAXN];
__device__ int    d_rowptr[MAXN];
__device__ int    d_col[MAXE];
__device__ float  d_dinv[MAXN];
__device__ __half d_g1[MAXN * 128];    // (x@W1)*dinv, fp16
__device__ __half d_out1[MAXN * 128];  // relu(layer1), fp16
__device__ __half d_g2[MAXN * 16];     // (out1@W2)*dinv, fp16

// ---------------- zero + dtype probe (fused) ----------------

__global__ void k_zero(const unsigned* __restrict__ ei_w, int n) {
    int i = blockIdx.x * blockDim.x + threadIdx.x;
    if (i < n) { d_counts[i] = 0; d_cursor[i] = 0; }
    if (i == 0) d_ctr = 0;
    if (blockIdx.x == 0 && threadIdx.x < 32) {
        int l = threadIdx.x;
        unsigned any = 0;
        #pragma unroll
        for (int j = 0; j < 8; j++) any |= ei_w[2 * (l + j * 32) + 1];
        unsigned ball = __ballot_sync(0xFFFFFFFFu, any != 0);
        if (l == 0) d_mode = (ball == 0) ? 1 : 0;
    }
}

__device__ __forceinline__ int load_idx(const void* ei, int e, int which, int i) {
    if (d_mode) return (int)((const long long*)ei)[(long long)which * e + i];
    return ((const int*)ei)[which * e + i];
}

// ---------------- degree count (4 edges per thread) ----------------

__global__ void k_deg(const void* __restrict__ ei, int e, int n) {
    int i4 = (blockIdx.x * blockDim.x + threadIdx.x) * 4;
    if (i4 >= e) return;
    if (d_mode == 0 && (e & 3) == 0 && i4 + 4 <= e) {
        int4 d = *(const int4*)((const int*)ei + e + i4);
        if ((unsigned)d.x < (unsigned)n) atomicAdd(&d_counts[d.x], 1);
        if ((unsigned)d.y < (unsigned)n) atomicAdd(&d_counts[d.y], 1);
        if ((unsigned)d.z < (unsigned)n) atomicAdd(&d_counts[d.z], 1);
        if ((unsigned)d.w < (unsigned)n) atomicAdd(&d_counts[d.w], 1);
    } else {
        int lim = min(i4 + 4, e);
        for (int j = i4; j < lim; j++) {
            int d = load_idx(ei, e, 1, j);
            if ((unsigned)d < (unsigned)n) atomicAdd(&d_counts[d], 1);
        }
    }
}

// ---------------- offset allocation: block-aggregated atomic bump ----------
// rowptr order is arbitrary (bucket content order doesn't matter for sums).

__global__ __launch_bounds__(256) void k_alloc(int n) {
    __shared__ int warp_base[8];
    __shared__ int block_base;
    int tid = threadIdx.x;
    int i = blockIdx.x * 256 + tid;
    int lane = tid & 31, wid = tid >> 5;

    int c = (i < n) ? d_counts[i] : 0;
    if (i < n) d_dinv[i] = rsqrtf((float)(c + 1));

    // warp inclusive scan of c
    int pref = c;
    #pragma unroll
    for (int off = 1; off < 32; off <<= 1) {
        int v = __shfl_up_sync(0xFFFFFFFFu, pref, off);
        if (lane >= off) pref += v;
    }
    if (lane == 31) warp_base[wid] = pref;   // warp totals
    __syncthreads();
    if (tid == 0) {
        int s = 0;
        #pragma unroll
        for (int w = 0; w < 8; w++) { int t = warp_base[w]; warp_base[w] = s; s += t; }
        block_base = atomicAdd(&d_ctr, s);   // one atomic per block
    }
    __syncthreads();
    if (i < n) d_rowptr[i] = block_base + warp_base[wid] + (pref - c);
}

// ---------------- CSR fill (4 edges per thread) ----------------

__global__ void k_fill(const void* __restrict__ ei, int e, int n) {
    int i4 = (blockIdx.x * blockDim.x + threadIdx.x) * 4;
    if (i4 >= e) return;
    if (d_mode == 0 && (e & 3) == 0 && i4 + 4 <= e) {
        int4 s = *(const int4*)((const int*)ei + i4);
        int4 d = *(const int4*)((const int*)ei + e + i4);
        if ((unsigned)d.x < (unsigned)n && (unsigned)s.x < (unsigned)n)
            d_col[d_rowptr[d.x] + atomicAdd(&d_cursor[d.x], 1)] = s.x;
        if ((unsigned)d.y < (unsigned)n && (unsigned)s.y < (unsigned)n)
            d_col[d_rowptr[d.y] + atomicAdd(&d_cursor[d.y], 1)] = s.y;
        if ((unsigned)d.z < (unsigned)n && (unsigned)s.z < (unsigned)n)
            d_col[d_rowptr[d.z] + atomicAdd(&d_cursor[d.z], 1)] = s.z;
        if ((unsigned)d.w < (unsigned)n && (unsigned)s.w < (unsigned)n)
            d_col[d_rowptr[d.w] + atomicAdd(&d_cursor[d.w], 1)] = s.w;
    } else {
        int lim = min(i4 + 4, e);
        for (int j = i4; j < lim; j++) {
            int s = load_idx(ei, e, 0, j);
            int d = load_idx(ei, e, 1, j);
            if ((unsigned)d < (unsigned)n && (unsigned)s < (unsigned)n)
                d_col[d_rowptr[d] + atomicAdd(&d_cursor[d], 1)] = s;
        }
    }
}

// ---------------- Layer 1 GEMM (tf32 tensor cores) ----------------

__device__ __forceinline__ unsigned f2tf(float f) {
    unsigned u;
    asm("cvt.rna.tf32.f32 %0, %1;" : "=r"(u) : "f"(f));
    return u;
}

__device__ __forceinline__ void mma_tf32(float* d, const unsigned* a, const unsigned* b) {
    asm volatile(
        "mma.sync.aligned.m16n8k8.row.col.f32.tf32.tf32.f32 "
        "{%0,%1,%2,%3}, {%4,%5,%6,%7}, {%8,%9}, {%0,%1,%2,%3};"
        : "+f"(d[0]), "+f"(d[1]), "+f"(d[2]), "+f"(d[3])
        : "r"(a[0]), "r"(a[1]), "r"(a[2]), "r"(a[3]), "r"(b[0]), "r"(b[1]));
}

__global__ __launch_bounds__(256) void k_gemm1_tc(const float* __restrict__ x,
                                                  const float* __restrict__ W1,
                                                  int n) {
    __shared__ float xs[128][36];
    __shared__ float ws[32][136];
    int tid = threadIdx.x;
    int lane = tid & 31;
    int wid = tid >> 5;
    int wm = wid & 1;
    int wn = wid >> 1;
    int row0 = blockIdx.x * 128;

    float acc[4][4][4];
    #pragma unroll
    for (int i = 0; i < 4; i++)
        #pragma unroll
        for (int j = 0; j < 4; j++)
            #pragma unroll
            for (int r = 0; r < 4; r++) acc[i][j][r] = 0.f;

    for (int k0 = 0; k0 < 256; k0 += 32) {
        if (k0) __syncthreads();
        #pragma unroll
        for (int i = 0; i < 4; i++) {
            int f = tid + i * 256;
            int r = f >> 3;
            int c = (f & 7) * 4;
            float4 v = make_float4(0.f, 0.f, 0.f, 0.f);
            if (row0 + r < n) v = *(const float4*)&x[(row0 + r) * 256 + k0 + c];
            xs[r][c] = v.x; xs[r][c + 1] = v.y; xs[r][c + 2] = v.z; xs[r][c + 3] = v.w;
        }
        #pragma unroll
        for (int i = 0; i < 4; i++) {
            int f = tid + i * 256;
            int kk = f >> 5;
            int c = (f & 31) * 4;
            float4 v = *(const float4*)&W1[(k0 + kk) * 128 + c];
            ws[kk][c] = v.x; ws[kk][c + 1] = v.y; ws[kk][c + 2] = v.z; ws[kk][c + 3] = v.w;
        }
        __syncthreads();

        #pragma unroll
        for (int ks = 0; ks < 4; ks++) {
            int k = ks * 8;
            unsigned a[4][4], b[4][2];
            int ar = lane >> 2;
            int ac = k + (lane & 3);
            #pragma unroll
            for (int mf = 0; mf < 4; mf++) {
                int r = wm * 64 + mf * 16 + ar;
                a[mf][0] = f2tf(xs[r][ac]);
                a[mf][1] = f2tf(xs[r + 8][ac]);
                a[mf][2] = f2tf(xs[r][ac + 4]);
                a[mf][3] = f2tf(xs[r + 8][ac + 4]);
            }
            int bc = wn * 32 + (lane >> 2);
            int br = k + (lane & 3);
            #pragma unroll
            for (int nf = 0; nf < 4; nf++) {
                b[nf][0] = f2tf(ws[br][bc + nf * 8]);
                b[nf][1] = f2tf(ws[br + 4][bc + nf * 8]);
            }
            #pragma unroll
            for (int mf = 0; mf < 4; mf++)
                #pragma unroll
                for (int nf = 0; nf < 4; nf++)
                    mma_tf32(acc[mf][nf], a[mf], b[nf]);
        }
    }

    #pragma unroll
    for (int mf = 0; mf < 4; mf++) {
        int r0 = row0 + wm * 64 + mf * 16 + (lane >> 2);
        int r1 = r0 + 8;
        float s0 = (r0 < n) ? d_dinv[r0] : 0.f;
        float s1 = (r1 < n) ? d_dinv[r1] : 0.f;
        #pragma unroll
        for (int nf = 0; nf < 4; nf++) {
            int c = wn * 32 + nf * 8 + (lane & 3) * 2;
            if (r0 < n)
                *(__half2*)&d_g1[r0 * 128 + c] =
                    __floats2half2_rn(acc[mf][nf][0] * s0, acc[mf][nf][1] * s0);
            if (r1 < n)
                *(__half2*)&d_g1[r1 * 128 + c] =
                    __floats2half2_rn(acc[mf][nf][2] * s1, acc[mf][nf][3] * s1);
        }
    }
}

// ---------------- fp16 helpers ----------------

__device__ __forceinline__ void acc_u4(float* acc, uint4 u) {
    float2 f0 = __half22float2(*(__half2*)&u.x);
    float2 f1 = __half22float2(*(__half2*)&u.y);
    float2 f2 = __half22float2(*(__half2*)&u.z);
    float2 f3 = __half22float2(*(__half2*)&u.w);
    acc[0] += f0.x; acc[1] += f0.y; acc[2] += f1.x; acc[3] += f1.y;
    acc[4] += f2.x; acc[5] += f2.y; acc[6] += f3.x; acc[7] += f3.y;
}

__device__ __forceinline__ float4 ld_g2h(int row, int part) {
    uint2 u = *(const uint2*)(d_g2 + row * 16 + part * 4);
    float2 f0 = __half22float2(*(__half2*)&u.x);
    float2 f1 = __half22float2(*(__half2*)&u.y);
    return make_float4(f0.x, f0.y, f1.x, f1.y);
}

// ---------------- Layer 1 aggregation: half-warp per node ----------------

__global__ __launch_bounds__(256) void k_agg1(const float* __restrict__ b1, int n) {
    int gw = (blockIdx.x * 256 + threadIdx.x) >> 4;   // node index
    int sl = threadIdx.x & 15;                         // sub-lane 0..15
    if (gw >= n) return;
    const __half* g1 = d_g1;
    int fo = sl * 8;

    float acc[8] = {};
    acc_u4(acc, *(const uint4*)(g1 + gw * 128 + fo));  // self-loop

    int e = d_rowptr[gw], end = e + d_counts[gw];
    for (; e + 4 <= end; e += 4) {
        int s0 = d_col[e], s1 = d_col[e + 1], s2 = d_col[e + 2], s3 = d_col[e + 3];
        uint4 u0 = *(const uint4*)(g1 + s0 * 128 + fo);
        uint4 u1 = *(const uint4*)(g1 + s1 * 128 + fo);
        uint4 u2 = *(const uint4*)(g1 + s2 * 128 + fo);
        uint4 u3 = *(const uint4*)(g1 + s3 * 128 + fo);
        acc_u4(acc, u0); acc_u4(acc, u1); acc_u4(acc, u2); acc_u4(acc, u3);
    }
    for (; e < end; e++)
        acc_u4(acc, *(const uint4*)(g1 + d_col[e] * 128 + fo));

    float sc = d_dinv[gw];
    float4 bb0 = ((const float4*)b1)[sl * 2];
    float4 bb1 = ((const float4*)b1)[sl * 2 + 1];
    float o0 = fmaxf(fmaf(sc, acc[0], bb0.x), 0.f);
    float o1 = fmaxf(fmaf(sc, acc[1], bb0.y), 0.f);
    float o2 = fmaxf(fmaf(sc, acc[2], bb0.z), 0.f);
    float o3 = fmaxf(fmaf(sc, acc[3], bb0.w), 0.f);
    float o4 = fmaxf(fmaf(sc, acc[4], bb1.x), 0.f);
    float o5 = fmaxf(fmaf(sc, acc[5], bb1.y), 0.f);
    float o6 = fmaxf(fmaf(sc, acc[6], bb1.z), 0.f);
    float o7 = fmaxf(fmaf(sc, acc[7], bb1.w), 0.f);
    __half2 p0 = __floats2half2_rn(o0, o1);
    __half2 p1 = __floats2half2_rn(o2, o3);
    __half2 p2 = __floats2half2_rn(o4, o5);
    __half2 p3 = __floats2half2_rn(o6, o7);
    uint4 u;
    u.x = *(unsigned*)&p0; u.y = *(unsigned*)&p1;
    u.z = *(unsigned*)&p2; u.w = *(unsigned*)&p3;
    *(uint4*)(d_out1 + gw * 128 + fo) = u;
}

// ---------------- Layer 2 GEMM: g2 = (out1 @ W2) * dinv ----------------

__global__ __launch_bounds__(256) void k_gemm2(const float* __restrict__ W2, int n) {
    int t = blockIdx.x * blockDim.x + threadIdx.x;
    int row = t >> 2;
    int part = t & 3;
    if (row >= n) return;
    const uint4* h = (const uint4*)(d_out1 + row * 128);
    const float4* w = (const float4*)W2;
    float4 acc = make_float4(0.f, 0.f, 0.f, 0.f);
    #pragma unroll
    for (int k8 = 0; k8 < 16; k8++) {
        uint4 u = h[k8];
        float2 f0 = __half22float2(*(__half2*)&u.x);
        float2 f1 = __half22float2(*(__half2*)&u.y);
        float2 f2 = __half22float2(*(__half2*)&u.z);
        float2 f3 = __half22float2(*(__half2*)&u.w);
        float a[8] = {f0.x, f0.y, f1.x, f1.y, f2.x, f2.y, f3.x, f3.y};
        #pragma unroll
        for (int i = 0; i < 8; i++) {
            float4 wv = w[(k8 * 8 + i) * 4 + part];
            acc.x += a[i] * wv.x;
            acc.y += a[i] * wv.y;
            acc.z += a[i] * wv.z;
            acc.w += a[i] * wv.w;
        }
    }
    float sc = d_dinv[row];
    __half2 p0 = __floats2half2_rn(acc.x * sc, acc.y * sc);
    __half2 p1 = __floats2half2_rn(acc.z * sc, acc.w * sc);
    uint2 u;
    u.x = *(unsigned*)&p0;
    u.y = *(unsigned*)&p1;
    *(uint2*)(d_g2 + row * 16 + part * 4) = u;
}

// ---------------- Layer 2 aggregation + final output ----------------

__global__ __launch_bounds__(256) void k_agg2(const float* __restrict__ b2,
                                              float* __restrict__ out, int n) {
    int t = blockIdx.x * blockDim.x + threadIdx.x;
    int row = t >> 2;
    int part = t & 3;
    if (row >= n) return;
    float4 acc = ld_g2h(row, part);
    int e = d_rowptr[row], end = e + d_counts[row];
    for (; e + 4 <= end; e += 4) {
        int s0 = d_col[e], s1 = d_col[e + 1], s2 = d_col[e + 2], s3 = d_col[e + 3];
        float4 v0 = ld_g2h(s0, part);
        float4 v1 = ld_g2h(s1, part);
        float4 v2 = ld_g2h(s2, part);
        float4 v3 = ld_g2h(s3, part);
        acc.x += (v0.x + v1.x) + (v2.x + v3.x);
        acc.y += (v0.y + v1.y) + (v2.y + v3.y);
        acc.z += (v0.z + v1.z) + (v2.z + v3.z);
        acc.w += (v0.w + v1.w) + (v2.w + v3.w);
    }
    for (; e < end; e++) {
        float4 v = ld_g2h(d_col[e], part);
        acc.x += v.x; acc.y += v.y; acc.z += v.z; acc.w += v.w;
    }
    float sc = d_dinv[row];
    float4 bb = ((const float4*)b2)[part];
    float4 o;
    o.x = fmaf(sc, acc.x, bb.x);
    o.y = fmaf(sc, acc.y, bb.y);
    o.z = fmaf(sc, acc.z, bb.z);
    o.w = fmaf(sc, acc.w, bb.w);
    *(float4*)&out[row * 16 + part * 4] = o;
}

// ---------------- launch ----------------

extern "C" void kernel_launch(void* const* d_in, const int* in_sizes, int n_in,
                              void* d_out, int out_size) {
    const float* x  = (const float*)d_in[0];
    const void*  ei = d_in[1];
    const float* W1 = (const float*)d_in[2];
    const float* b1 = (const float*)d_in[3];
    const float* W2 = (const float*)d_in[4];
    const float* b2 = (const float*)d_in[5];
    float* out = (float*)d_out;

    int n = in_sizes[0] / 256;
    int e = in_sizes[1] / 2;
    int nv = (e + 3) / 4;   // 4 edges per thread

    k_zero <<<(n + 255) / 256, 256>>>((const unsigned*)ei, n);
    k_deg  <<<(nv + 255) / 256, 256>>>(ei, e, n);
    k_alloc<<<(n + 255) / 256, 256>>>(n);
    k_fill <<<(nv + 255) / 256, 256>>>(ei, e, n);

    k_gemm1_tc<<<(n + 127) / 128, 256>>>(x, W1, n);
    k_agg1 <<<(n * 16 + 255) / 256, 256>>>(b1, n);
    k_gemm2<<<(n * 4 + 255) / 256, 256>>>(W2, n);
    k_agg2 <<<(n * 4 + 255) / 256, 256>>>(b2, out, n);
}

// round 12
// speedup vs baseline: 1.9337x; 1.0238x over previous
#include <cuda_runtime.h>
#include <cuda_fp16.h>

// ---------------------------------------------------------------------------
// 2-layer GCN, pull aggregation over per-call CSR-by-dst.
//   g = (h @ W) * dinv[row];  agg[d] = dinv[d]*(sum_in g[src] + g[d])
// GEMM1 on tf32 tensor cores. g1/out1/g2 fp16 (fp32 accumulate).
// CSR: rank trick -- k_deg's atomicAdd return IS the in-bucket rank, so
// k_fill is atomic-free. Offsets via block-aggregated atomic bump (no scan).
// edge_index dtype probed at runtime (int32 vs int64).
// ---------------------------------------------------------------------------

#define MAXN 100000
#define MAXE 1600000

__device__ int    d_mode;
__device__ int    d_ctr;
__device__ int    d_counts[MAXN];
__device__ int    d_rowptr[MAXN];
__device__ int    d_rank[MAXE];
__device__ int    d_col[MAXE];
__device__ float  d_dinv[MAXN];
__device__ __half d_g1[MAXN * 128];    // (x@W1)*dinv, fp16
__device__ __half d_out1[MAXN * 128];  // relu(layer1), fp16
__device__ __half d_g2[MAXN * 16];     // (out1@W2)*dinv, fp16

// ---------------- zero + dtype probe (fused) ----------------

__global__ void k_zero(const unsigned* __restrict__ ei_w, int n) {
    int i = blockIdx.x * blockDim.x + threadIdx.x;
    if (i < n) d_counts[i] = 0;
    if (i == 0) d_ctr = 0;
    if (blockIdx.x == 0 && threadIdx.x < 32) {
        int l = threadIdx.x;
        unsigned any = 0;
        #pragma unroll
        for (int j = 0; j < 8; j++) any |= ei_w[2 * (l + j * 32) + 1];
        unsigned ball = __ballot_sync(0xFFFFFFFFu, any != 0);
        if (l == 0) d_mode = (ball == 0) ? 1 : 0;
    }
}

__device__ __forceinline__ int load_idx(const void* ei, int e, int which, int i) {
    if (d_mode) return (int)((const long long*)ei)[(long long)which * e + i];
    return ((const int*)ei)[which * e + i];
}

// ------------- degree count + per-edge rank (4 edges per thread) -----------

__global__ void k_deg(const void* __restrict__ ei, int e, int n) {
    int i4 = (blockIdx.x * blockDim.x + threadIdx.x) * 4;
    if (i4 >= e) return;
    if (d_mode == 0 && (e & 3) == 0 && i4 + 4 <= e) {
        int4 d = *(const int4*)((const int*)ei + e + i4);
        int4 r = make_int4(0, 0, 0, 0);
        if ((unsigned)d.x < (unsigned)n) r.x = atomicAdd(&d_counts[d.x], 1);
        if ((unsigned)d.y < (unsigned)n) r.y = atomicAdd(&d_counts[d.y], 1);
        if ((unsigned)d.z < (unsigned)n) r.z = atomicAdd(&d_counts[d.z], 1);
        if ((unsigned)d.w < (unsigned)n) r.w = atomicAdd(&d_counts[d.w], 1);
        *(int4*)&d_rank[i4] = r;
    } else {
        int lim = min(i4 + 4, e);
        for (int j = i4; j < lim; j++) {
            int d = load_idx(ei, e, 1, j);
            int r = 0;
            if ((unsigned)d < (unsigned)n) r = atomicAdd(&d_counts[d], 1);
            d_rank[j] = r;
        }
    }
}

// ---------------- offset allocation: block-aggregated atomic bump ----------

__global__ __launch_bounds__(256) void k_alloc(int n) {
    __shared__ int warp_base[8];
    __shared__ int block_base;
    int tid = threadIdx.x;
    int i = blockIdx.x * 256 + tid;
    int lane = tid & 31, wid = tid >> 5;

    int c = (i < n) ? d_counts[i] : 0;
    if (i < n) d_dinv[i] = rsqrtf((float)(c + 1));

    int pref = c;
    #pragma unroll
    for (int off = 1; off < 32; off <<= 1) {
        int v = __shfl_up_sync(0xFFFFFFFFu, pref, off);
        if (lane >= off) pref += v;
    }
    if (lane == 31) warp_base[wid] = pref;
    __syncthreads();
    if (tid == 0) {
        int s = 0;
        #pragma unroll
        for (int w = 0; w < 8; w++) { int t = warp_base[w]; warp_base[w] = s; s += t; }
        block_base = atomicAdd(&d_ctr, s);
    }
    __syncthreads();
    if (i < n) d_rowptr[i] = block_base + warp_base[wid] + (pref - c);
}

// ---------------- CSR fill: atomic-free via precomputed ranks ----------------

__global__ void k_fill(const void* __restrict__ ei, int e, int n) {
    int i4 = (blockIdx.x * blockDim.x + threadIdx.x) * 4;
    if (i4 >= e) return;
    if (d_mode == 0 && (e & 3) == 0 && i4 + 4 <= e) {
        int4 s = *(const int4*)((const int*)ei + i4);
        int4 d = *(const int4*)((const int*)ei + e + i4);
        int4 r = *(const int4*)&d_rank[i4];
        if ((unsigned)d.x < (unsigned)n && (unsigned)s.x < (unsigned)n)
            d_col[d_rowptr[d.x] + r.x] = s.x;
        if ((unsigned)d.y < (unsigned)n && (unsigned)s.y < (unsigned)n)
            d_col[d_rowptr[d.y] + r.y] = s.y;
        if ((unsigned)d.z < (unsigned)n && (unsigned)s.z < (unsigned)n)
            d_col[d_rowptr[d.z] + r.z] = s.z;
        if ((unsigned)d.w < (unsigned)n && (unsigned)s.w < (unsigned)n)
            d_col[d_rowptr[d.w] + r.w] = s.w;
    } else {
        int lim = min(i4 + 4, e);
        for (int j = i4; j < lim; j++) {
            int s = load_idx(ei, e, 0, j);
            int d = load_idx(ei, e, 1, j);
            if ((unsigned)d < (unsigned)n && (unsigned)s < (unsigned)n)
                d_col[d_rowptr[d] + d_rank[j]] = s;
        }
    }
}

// ---------------- Layer 1 GEMM (tf32 tensor cores) ----------------

__device__ __forceinline__ unsigned f2tf(float f) {
    unsigned u;
    asm("cvt.rna.tf32.f32 %0, %1;" : "=r"(u) : "f"(f));
    return u;
}

__device__ __forceinline__ void mma_tf32(float* d, const unsigned* a, const unsigned* b) {
    asm volatile(
        "mma.sync.aligned.m16n8k8.row.col.f32.tf32.tf32.f32 "
        "{%0,%1,%2,%3}, {%4,%5,%6,%7}, {%8,%9}, {%0,%1,%2,%3};"
        : "+f"(d[0]), "+f"(d[1]), "+f"(d[2]), "+f"(d[3])
        : "r"(a[0]), "r"(a[1]), "r"(a[2]), "r"(a[3]), "r"(b[0]), "r"(b[1]));
}

__global__ __launch_bounds__(256) void k_gemm1_tc(const float* __restrict__ x,
                                                  const float* __restrict__ W1,
                                                  int n) {
    __shared__ float xs[128][36];
    __shared__ float ws[32][136];
    int tid = threadIdx.x;
    int lane = tid & 31;
    int wid = tid >> 5;
    int wm = wid & 1;
    int wn = wid >> 1;
    int row0 = blockIdx.x * 128;

    float acc[4][4][4];
    #pragma unroll
    for (int i = 0; i < 4; i++)
        #pragma unroll
        for (int j = 0; j < 4; j++)
            #pragma unroll
            for (int r = 0; r < 4; r++) acc[i][j][r] = 0.f;

    for (int k0 = 0; k0 < 256; k0 += 32) {
        if (k0) __syncthreads();
        #pragma unroll
        for (int i = 0; i < 4; i++) {
            int f = tid + i * 256;
            int r = f >> 3;
            int c = (f & 7) * 4;
            float4 v = make_float4(0.f, 0.f, 0.f, 0.f);
            if (row0 + r < n) v = *(const float4*)&x[(row0 + r) * 256 + k0 + c];
            xs[r][c] = v.x; xs[r][c + 1] = v.y; xs[r][c + 2] = v.z; xs[r][c + 3] = v.w;
        }
        #pragma unroll
        for (int i = 0; i < 4; i++) {
            int f = tid + i * 256;
            int kk = f >> 5;
            int c = (f & 31) * 4;
            float4 v = *(const float4*)&W1[(k0 + kk) * 128 + c];
            ws[kk][c] = v.x; ws[kk][c + 1] = v.y; ws[kk][c + 2] = v.z; ws[kk][c + 3] = v.w;
        }
        __syncthreads();

        #pragma unroll
        for (int ks = 0; ks < 4; ks++) {
            int k = ks * 8;
            unsigned a[4][4], b[4][2];
            int ar = lane >> 2;
            int ac = k + (lane & 3);
            #pragma unroll
            for (int mf = 0; mf < 4; mf++) {
                int r = wm * 64 + mf * 16 + ar;
                a[mf][0] = f2tf(xs[r][ac]);
                a[mf][1] = f2tf(xs[r + 8][ac]);
                a[mf][2] = f2tf(xs[r][ac + 4]);
                a[mf][3] = f2tf(xs[r + 8][ac + 4]);
            }
            int bc = wn * 32 + (lane >> 2);
            int br = k + (lane & 3);
            #pragma unroll
            for (int nf = 0; nf < 4; nf++) {
                b[nf][0] = f2tf(ws[br][bc + nf * 8]);
                b[nf][1] = f2tf(ws[br + 4][bc + nf * 8]);
            }
            #pragma unroll
            for (int mf = 0; mf < 4; mf++)
                #pragma unroll
                for (int nf = 0; nf < 4; nf++)
                    mma_tf32(acc[mf][nf], a[mf], b[nf]);
        }
    }

    #pragma unroll
    for (int mf = 0; mf < 4; mf++) {
        int r0 = row0 + wm * 64 + mf * 16 + (lane >> 2);
        int r1 = r0 + 8;
        float s0 = (r0 < n) ? d_dinv[r0] : 0.f;
        float s1 = (r1 < n) ? d_dinv[r1] : 0.f;
        #pragma unroll
        for (int nf = 0; nf < 4; nf++) {
            int c = wn * 32 + nf * 8 + (lane & 3) * 2;
            if (r0 < n)
                *(__half2*)&d_g1[r0 * 128 + c] =
                    __floats2half2_rn(acc[mf][nf][0] * s0, acc[mf][nf][1] * s0);
            if (r1 < n)
                *(__half2*)&d_g1[r1 * 128 + c] =
                    __floats2half2_rn(acc[mf][nf][2] * s1, acc[mf][nf][3] * s1);
        }
    }
}

// ---------------- fp16 helpers ----------------

__device__ __forceinline__ void acc_u4(float* acc, uint4 u) {
    float2 f0 = __half22float2(*(__half2*)&u.x);
    float2 f1 = __half22float2(*(__half2*)&u.y);
    float2 f2 = __half22float2(*(__half2*)&u.z);
    float2 f3 = __half22float2(*(__half2*)&u.w);
    acc[0] += f0.x; acc[1] += f0.y; acc[2] += f1.x; acc[3] += f1.y;
    acc[4] += f2.x; acc[5] += f2.y; acc[6] += f3.x; acc[7] += f3.y;
}

__device__ __forceinline__ float4 ld_g2h(int row, int part) {
    uint2 u = *(const uint2*)(d_g2 + row * 16 + part * 4);
    float2 f0 = __half22float2(*(__half2*)&u.x);
    float2 f1 = __half22float2(*(__half2*)&u.y);
    return make_float4(f0.x, f0.y, f1.x, f1.y);
}

// ---------------- Layer 1 aggregation: half-warp per node ----------------

__global__ __launch_bounds__(256) void k_agg1(const float* __restrict__ b1, int n) {
    int gw = (blockIdx.x * 256 + threadIdx.x) >> 4;
    int sl = threadIdx.x & 15;
    if (gw >= n) return;
    const __half* g1 = d_g1;
    int fo = sl * 8;

    float acc[8] = {};
    acc_u4(acc, *(const uint4*)(g1 + gw * 128 + fo));  // self-loop

    int e = d_rowptr[gw], end = e + d_counts[gw];
    for (; e + 4 <= end; e += 4) {
        int s0 = d_col[e], s1 = d_col[e + 1], s2 = d_col[e + 2], s3 = d_col[e + 3];
        uint4 u0 = *(const uint4*)(g1 + s0 * 128 + fo);
        uint4 u1 = *(const uint4*)(g1 + s1 * 128 + fo);
        uint4 u2 = *(const uint4*)(g1 + s2 * 128 + fo);
        uint4 u3 = *(const uint4*)(g1 + s3 * 128 + fo);
        acc_u4(acc, u0); acc_u4(acc, u1); acc_u4(acc, u2); acc_u4(acc, u3);
    }
    for (; e < end; e++)
        acc_u4(acc, *(const uint4*)(g1 + d_col[e] * 128 + fo));

    float sc = d_dinv[gw];
    float4 bb0 = ((const float4*)b1)[sl * 2];
    float4 bb1 = ((const float4*)b1)[sl * 2 + 1];
    float o0 = fmaxf(fmaf(sc, acc[0], bb0.x), 0.f);
    float o1 = fmaxf(fmaf(sc, acc[1], bb0.y), 0.f);
    float o2 = fmaxf(fmaf(sc, acc[2], bb0.z), 0.f);
    float o3 = fmaxf(fmaf(sc, acc[3], bb0.w), 0.f);
    float o4 = fmaxf(fmaf(sc, acc[4], bb1.x), 0.f);
    float o5 = fmaxf(fmaf(sc, acc[5], bb1.y), 0.f);
    float o6 = fmaxf(fmaf(sc, acc[6], bb1.z), 0.f);
    float o7 = fmaxf(fmaf(sc, acc[7], bb1.w), 0.f);
    __half2 p0 = __floats2half2_rn(o0, o1);
    __half2 p1 = __floats2half2_rn(o2, o3);
    __half2 p2 = __floats2half2_rn(o4, o5);
    __half2 p3 = __floats2half2_rn(o6, o7);
    uint4 u;
    u.x = *(unsigned*)&p0; u.y = *(unsigned*)&p1;
    u.z = *(unsigned*)&p2; u.w = *(unsigned*)&p3;
    *(uint4*)(d_out1 + gw * 128 + fo) = u;
}

// ---------------- Layer 2 GEMM: g2 = (out1 @ W2) * dinv ----------------

__global__ __launch_bounds__(256) void k_gemm2(const float* __restrict__ W2, int n) {
    int t = blockIdx.x * blockDim.x + threadIdx.x;
    int row = t >> 2;
    int part = t & 3;
    if (row >= n) return;
    const uint4* h = (const uint4*)(d_out1 + row * 128);
    const float4* w = (const float4*)W2;
    float4 acc = make_float4(0.f, 0.f, 0.f, 0.f);
    #pragma unroll
    for (int k8 = 0; k8 < 16; k8++) {
        uint4 u = h[k8];
        float2 f0 = __half22float2(*(__half2*)&u.x);
        float2 f1 = __half22float2(*(__half2*)&u.y);
        float2 f2 = __half22float2(*(__half2*)&u.z);
        float2 f3 = __half22float2(*(__half2*)&u.w);
        float a[8] = {f0.x, f0.y, f1.x, f1.y, f2.x, f2.y, f3.x, f3.y};
        #pragma unroll
        for (int i = 0; i < 8; i++) {
            float4 wv = w[(k8 * 8 + i) * 4 + part];
            acc.x += a[i] * wv.x;
            acc.y += a[i] * wv.y;
            acc.z += a[i] * wv.z;
            acc.w += a[i] * wv.w;
        }
    }
    float sc = d_dinv[row];
    __half2 p0 = __floats2half2_rn(acc.x * sc, acc.y * sc);
    __half2 p1 = __floats2half2_rn(acc.z * sc, acc.w * sc);
    uint2 u;
    u.x = *(unsigned*)&p0;
    u.y = *(unsigned*)&p1;
    *(uint2*)(d_g2 + row * 16 + part * 4) = u;
}

// ---------------- Layer 2 aggregation + final output ----------------

__global__ __launch_bounds__(256) void k_agg2(const float* __restrict__ b2,
                                              float* __restrict__ out, int n) {
    int t = blockIdx.x * blockDim.x + threadIdx.x;
    int row = t >> 2;
    int part = t & 3;
    if (row >= n) return;
    float4 acc = ld_g2h(row, part);
    int e = d_rowptr[row], end = e + d_counts[row];
    for (; e + 4 <= end; e += 4) {
        int s0 = d_col[e], s1 = d_col[e + 1], s2 = d_col[e + 2], s3 = d_col[e + 3];
        float4 v0 = ld_g2h(s0, part);
        float4 v1 = ld_g2h(s1, part);
        float4 v2 = ld_g2h(s2, part);
        float4 v3 = ld_g2h(s3, part);
        acc.x += (v0.x + v1.x) + (v2.x + v3.x);
        acc.y += (v0.y + v1.y) + (v2.y + v3.y);
        acc.z += (v0.z + v1.z) + (v2.z + v3.z);
        acc.w += (v0.w + v1.w) + (v2.w + v3.w);
    }
    for (; e < end; e++) {
        float4 v = ld_g2h(d_col[e], part);
        acc.x += v.x; acc.y += v.y; acc.z += v.z; acc.w += v.w;
    }
    float sc = d_dinv[row];
    float4 bb = ((const float4*)b2)[part];
    float4 o;
    o.x = fmaf(sc, acc.x, bb.x);
    o.y = fmaf(sc, acc.y, bb.y);
    o.z = fmaf(sc, acc.z, bb.z);
    o.w = fmaf(sc, acc.w, bb.w);
    *(float4*)&out[row * 16 + part * 4] = o;
}

// ---------------- launch ----------------

extern "C" void kernel_launch(void* const* d_in, const int* in_sizes, int n_in,
                              void* d_out, int out_size) {
    const float* x  = (const float*)d_in[0];
    const void*  ei = d_in[1];
    const float* W1 = (const float*)d_in[2];
    const float* b1 = (const float*)d_in[3];
    const float* W2 = (const float*)d_in[4];
    const float* b2 = (const float*)d_in[5];
    float* out = (float*)d_out;

    int n = in_sizes[0] / 256;
    int e = in_sizes[1] / 2;
    int nv = (e + 3) / 4;

    k_zero <<<(n + 255) / 256, 256>>>((const unsigned*)ei, n);
    k_deg  <<<(nv + 255) / 256, 256>>>(ei, e, n);
    k_alloc<<<(n + 255) / 256, 256>>>(n);
    k_fill <<<(nv + 255) / 256, 256>>>(ei, e, n);

    k_gemm1_tc<<<(n + 127) / 128, 256>>>(x, W1, n);
    k_agg1 <<<(n * 16 + 255) / 256, 256>>>(b1, n);
    k_gemm2<<<(n * 4 + 255) / 256, 256>>>(W2, n);
    k_agg2 <<<(n * 4 + 255) / 256, 256>>>(b2, out, n);
}

// round 13
// speedup vs baseline: 1.9691x; 1.0183x over previous
#include <cuda_runtime.h>
#include <cuda_fp16.h>

// ---------------------------------------------------------------------------
// 2-layer GCN, pull aggregation over per-call CSR-by-dst.
//   g = (h @ W) * dinv[row];  agg[d] = dinv[d]*(sum_in g[src] + g[d])
// GEMM1 on tf32 tensor cores. g1/out1/g2 fp16 (fp32 accumulate).
// CSR: rank trick (k_deg's atomicAdd return = in-bucket rank) -> atomic-free
// fill. Offsets via block-aggregated atomic bump. k_fill and k_gemm1 run on
// forked streams (independent; complementary resource profiles).
// edge_index dtype probed at runtime (int32 vs int64).
// ---------------------------------------------------------------------------

#define MAXN 100000
#define MAXE 1600000

__device__ int    d_mode;
__device__ int    d_ctr;
__device__ int    d_counts[MAXN];
__device__ int    d_rowptr[MAXN];
__device__ int    d_rank[MAXE];
__device__ int    d_col[MAXE];
__device__ float  d_dinv[MAXN];
__device__ __half d_g1[MAXN * 128];    // (x@W1)*dinv, fp16
__device__ __half d_out1[MAXN * 128];  // relu(layer1), fp16
__device__ __half d_g2[MAXN * 16];     // (out1@W2)*dinv, fp16

// ---------------- zero + dtype probe (fused) ----------------

__global__ void k_zero(const unsigned* __restrict__ ei_w, int n) {
    int i = blockIdx.x * blockDim.x + threadIdx.x;
    if (i < n) d_counts[i] = 0;
    if (i == 0) d_ctr = 0;
    if (blockIdx.x == 0 && threadIdx.x < 32) {
        int l = threadIdx.x;
        unsigned any = 0;
        #pragma unroll
        for (int j = 0; j < 8; j++) any |= ei_w[2 * (l + j * 32) + 1];
        unsigned ball = __ballot_sync(0xFFFFFFFFu, any != 0);
        if (l == 0) d_mode = (ball == 0) ? 1 : 0;
    }
}

__device__ __forceinline__ int load_idx(const void* ei, int e, int which, int i) {
    if (d_mode) return (int)((const long long*)ei)[(long long)which * e + i];
    return ((const int*)ei)[which * e + i];
}

// ------------- degree count + per-edge rank (4 edges per thread) -----------

__global__ void k_deg(const void* __restrict__ ei, int e, int n) {
    int i4 = (blockIdx.x * blockDim.x + threadIdx.x) * 4;
    if (i4 >= e) return;
    if (d_mode == 0 && (e & 3) == 0 && i4 + 4 <= e) {
        int4 d = *(const int4*)((const int*)ei + e + i4);
        int4 r = make_int4(0, 0, 0, 0);
        if ((unsigned)d.x < (unsigned)n) r.x = atomicAdd(&d_counts[d.x], 1);
        if ((unsigned)d.y < (unsigned)n) r.y = atomicAdd(&d_counts[d.y], 1);
        if ((unsigned)d.z < (unsigned)n) r.z = atomicAdd(&d_counts[d.z], 1);
        if ((unsigned)d.w < (unsigned)n) r.w = atomicAdd(&d_counts[d.w], 1);
        *(int4*)&d_rank[i4] = r;
    } else {
        int lim = min(i4 + 4, e);
        for (int j = i4; j < lim; j++) {
            int d = load_idx(ei, e, 1, j);
            int r = 0;
            if ((unsigned)d < (unsigned)n) r = atomicAdd(&d_counts[d], 1);
            d_rank[j] = r;
        }
    }
}

// ---------------- offset allocation: block-aggregated atomic bump ----------

__global__ __launch_bounds__(256) void k_alloc(int n) {
    __shared__ int warp_base[8];
    __shared__ int block_base;
    int tid = threadIdx.x;
    int i = blockIdx.x * 256 + tid;
    int lane = tid & 31, wid = tid >> 5;

    int c = (i < n) ? d_counts[i] : 0;
    if (i < n) d_dinv[i] = rsqrtf((float)(c + 1));

    int pref = c;
    #pragma unroll
    for (int off = 1; off < 32; off <<= 1) {
        int v = __shfl_up_sync(0xFFFFFFFFu, pref, off);
        if (lane >= off) pref += v;
    }
    if (lane == 31) warp_base[wid] = pref;
    __syncthreads();
    if (tid == 0) {
        int s = 0;
        #pragma unroll
        for (int w = 0; w < 8; w++) { int t = warp_base[w]; warp_base[w] = s; s += t; }
        block_base = atomicAdd(&d_ctr, s);
    }
    __syncthreads();
    if (i < n) d_rowptr[i] = block_base + warp_base[wid] + (pref - c);
}

// ---------------- CSR fill: atomic-free via precomputed ranks ----------------

__global__ void k_fill(const void* __restrict__ ei, int e, int n) {
    int i4 = (blockIdx.x * blockDim.x + threadIdx.x) * 4;
    if (i4 >= e) return;
    if (d_mode == 0 && (e & 3) == 0 && i4 + 4 <= e) {
        int4 s = *(const int4*)((const int*)ei + i4);
        int4 d = *(const int4*)((const int*)ei + e + i4);
        int4 r = *(const int4*)&d_rank[i4];
        if ((unsigned)d.x < (unsigned)n && (unsigned)s.x < (unsigned)n)
            d_col[d_rowptr[d.x] + r.x] = s.x;
        if ((unsigned)d.y < (unsigned)n && (unsigned)s.y < (unsigned)n)
            d_col[d_rowptr[d.y] + r.y] = s.y;
        if ((unsigned)d.z < (unsigned)n && (unsigned)s.z < (unsigned)n)
            d_col[d_rowptr[d.z] + r.z] = s.z;
        if ((unsigned)d.w < (unsigned)n && (unsigned)s.w < (unsigned)n)
            d_col[d_rowptr[d.w] + r.w] = s.w;
    } else {
        int lim = min(i4 + 4, e);
        for (int j = i4; j < lim; j++) {
            int s = load_idx(ei, e, 0, j);
            int d = load_idx(ei, e, 1, j);
            if ((unsigned)d < (unsigned)n && (unsigned)s < (unsigned)n)
                d_col[d_rowptr[d] + d_rank[j]] = s;
        }
    }
}

// ---------------- Layer 1 GEMM (tf32 tensor cores) ----------------

__device__ __forceinline__ unsigned f2tf(float f) {
    unsigned u;
    asm("cvt.rna.tf32.f32 %0, %1;" : "=r"(u) : "f"(f));
    return u;
}

__device__ __forceinline__ void mma_tf32(float* d, const unsigned* a, const unsigned* b) {
    asm volatile(
        "mma.sync.aligned.m16n8k8.row.col.f32.tf32.tf32.f32 "
        "{%0,%1,%2,%3}, {%4,%5,%6,%7}, {%8,%9}, {%0,%1,%2,%3};"
        : "+f"(d[0]), "+f"(d[1]), "+f"(d[2]), "+f"(d[3])
        : "r"(a[0]), "r"(a[1]), "r"(a[2]), "r"(a[3]), "r"(b[0]), "r"(b[1]));
}

__global__ __launch_bounds__(256) void k_gemm1_tc(const float* __restrict__ x,
                                                  const float* __restrict__ W1,
                                                  int n) {
    __shared__ float xs[128][36];
    __shared__ float ws[32][136];
    int tid = threadIdx.x;
    int lane = tid & 31;
    int wid = tid >> 5;
    int wm = wid & 1;
    int wn = wid >> 1;
    int row0 = blockIdx.x * 128;

    float acc[4][4][4];
    #pragma unroll
    for (int i = 0; i < 4; i++)
        #pragma unroll
        for (int j = 0; j < 4; j++)
            #pragma unroll
            for (int r = 0; r < 4; r++) acc[i][j][r] = 0.f;

    for (int k0 = 0; k0 < 256; k0 += 32) {
        if (k0) __syncthreads();
        #pragma unroll
        for (int i = 0; i < 4; i++) {
            int f = tid + i * 256;
            int r = f >> 3;
            int c = (f & 7) * 4;
            float4 v = make_float4(0.f, 0.f, 0.f, 0.f);
            if (row0 + r < n) v = *(const float4*)&x[(row0 + r) * 256 + k0 + c];
            xs[r][c] = v.x; xs[r][c + 1] = v.y; xs[r][c + 2] = v.z; xs[r][c + 3] = v.w;
        }
        #pragma unroll
        for (int i = 0; i < 4; i++) {
            int f = tid + i * 256;
            int kk = f >> 5;
            int c = (f & 31) * 4;
            float4 v = *(const float4*)&W1[(k0 + kk) * 128 + c];
            ws[kk][c] = v.x; ws[kk][c + 1] = v.y; ws[kk][c + 2] = v.z; ws[kk][c + 3] = v.w;
        }
        __syncthreads();

        #pragma unroll
        for (int ks = 0; ks < 4; ks++) {
            int k = ks * 8;
            unsigned a[4][4], b[4][2];
            int ar = lane >> 2;
            int ac = k + (lane & 3);
            #pragma unroll
            for (int mf = 0; mf < 4; mf++) {
                int r = wm * 64 + mf * 16 + ar;
                a[mf][0] = f2tf(xs[r][ac]);
                a[mf][1] = f2tf(xs[r + 8][ac]);
                a[mf][2] = f2tf(xs[r][ac + 4]);
                a[mf][3] = f2tf(xs[r + 8][ac + 4]);
            }
            int bc = wn * 32 + (lane >> 2);
            int br = k + (lane & 3);
            #pragma unroll
            for (int nf = 0; nf < 4; nf++) {
                b[nf][0] = f2tf(ws[br][bc + nf * 8]);
                b[nf][1] = f2tf(ws[br + 4][bc + nf * 8]);
            }
            #pragma unroll
            for (int mf = 0; mf < 4; mf++)
                #pragma unroll
                for (int nf = 0; nf < 4; nf++)
                    mma_tf32(acc[mf][nf], a[mf], b[nf]);
        }
    }

    #pragma unroll
    for (int mf = 0; mf < 4; mf++) {
        int r0 = row0 + wm * 64 + mf * 16 + (lane >> 2);
        int r1 = r0 + 8;
        float s0 = (r0 < n) ? d_dinv[r0] : 0.f;
        float s1 = (r1 < n) ? d_dinv[r1] : 0.f;
        #pragma unroll
        for (int nf = 0; nf < 4; nf++) {
            int c = wn * 32 + nf * 8 + (lane & 3) * 2;
            if (r0 < n)
                *(__half2*)&d_g1[r0 * 128 + c] =
                    __floats2half2_rn(acc[mf][nf][0] * s0, acc[mf][nf][1] * s0);
            if (r1 < n)
                *(__half2*)&d_g1[r1 * 128 + c] =
                    __floats2half2_rn(acc[mf][nf][2] * s1, acc[mf][nf][3] * s1);
        }
    }
}

// ---------------- fp16 helpers ----------------

__device__ __forceinline__ void acc_u4(float* acc, uint4 u) {
    float2 f0 = __half22float2(*(__half2*)&u.x);
    float2 f1 = __half22float2(*(__half2*)&u.y);
    float2 f2 = __half22float2(*(__half2*)&u.z);
    float2 f3 = __half22float2(*(__half2*)&u.w);
    acc[0] += f0.x; acc[1] += f0.y; acc[2] += f1.x; acc[3] += f1.y;
    acc[4] += f2.x; acc[5] += f2.y; acc[6] += f3.x; acc[7] += f3.y;
}

__device__ __forceinline__ float4 ld_g2h(int row, int part) {
    uint2 u = *(const uint2*)(d_g2 + row * 16 + part * 4);
    float2 f0 = __half22float2(*(__half2*)&u.x);
    float2 f1 = __half22float2(*(__half2*)&u.y);
    return make_float4(f0.x, f0.y, f1.x, f1.y);
}

// ---------------- Layer 1 aggregation: half-warp per node ----------------

__global__ __launch_bounds__(256) void k_agg1(const float* __restrict__ b1, int n) {
    int gw = (blockIdx.x * 256 + threadIdx.x) >> 4;
    int sl = threadIdx.x & 15;
    if (gw >= n) return;
    const __half* g1 = d_g1;
    int fo = sl * 8;

    float acc[8] = {};
    acc_u4(acc, *(const uint4*)(g1 + gw * 128 + fo));  // self-loop

    int e = d_rowptr[gw], end = e + d_counts[gw];
    for (; e + 4 <= end; e += 4) {
        int s0 = d_col[e], s1 = d_col[e + 1], s2 = d_col[e + 2], s3 = d_col[e + 3];
        uint4 u0 = *(const uint4*)(g1 + s0 * 128 + fo);
        uint4 u1 = *(const uint4*)(g1 + s1 * 128 + fo);
        uint4 u2 = *(const uint4*)(g1 + s2 * 128 + fo);
        uint4 u3 = *(const uint4*)(g1 + s3 * 128 + fo);
        acc_u4(acc, u0); acc_u4(acc, u1); acc_u4(acc, u2); acc_u4(acc, u3);
    }
    for (; e < end; e++)
        acc_u4(acc, *(const uint4*)(g1 + d_col[e] * 128 + fo));

    float sc = d_dinv[gw];
    float4 bb0 = ((const float4*)b1)[sl * 2];
    float4 bb1 = ((const float4*)b1)[sl * 2 + 1];
    float o0 = fmaxf(fmaf(sc, acc[0], bb0.x), 0.f);
    float o1 = fmaxf(fmaf(sc, acc[1], bb0.y), 0.f);
    float o2 = fmaxf(fmaf(sc, acc[2], bb0.z), 0.f);
    float o3 = fmaxf(fmaf(sc, acc[3], bb0.w), 0.f);
    float o4 = fmaxf(fmaf(sc, acc[4], bb1.x), 0.f);
    float o5 = fmaxf(fmaf(sc, acc[5], bb1.y), 0.f);
    float o6 = fmaxf(fmaf(sc, acc[6], bb1.z), 0.f);
    float o7 = fmaxf(fmaf(sc, acc[7], bb1.w), 0.f);
    __half2 p0 = __floats2half2_rn(o0, o1);
    __half2 p1 = __floats2half2_rn(o2, o3);
    __half2 p2 = __floats2half2_rn(o4, o5);
    __half2 p3 = __floats2half2_rn(o6, o7);
    uint4 u;
    u.x = *(unsigned*)&p0; u.y = *(unsigned*)&p1;
    u.z = *(unsigned*)&p2; u.w = *(unsigned*)&p3;
    *(uint4*)(d_out1 + gw * 128 + fo) = u;
}

// ---------------- Layer 2 GEMM: g2 = (out1 @ W2) * dinv ----------------

__global__ __launch_bounds__(256) void k_gemm2(const float* __restrict__ W2, int n) {
    int t = blockIdx.x * blockDim.x + threadIdx.x;
    int row = t >> 2;
    int part = t & 3;
    if (row >= n) return;
    const uint4* h = (const uint4*)(d_out1 + row * 128);
    const float4* w = (const float4*)W2;
    float4 acc = make_float4(0.f, 0.f, 0.f, 0.f);
    #pragma unroll
    for (int k8 = 0; k8 < 16; k8++) {
        uint4 u = h[k8];
        float2 f0 = __half22float2(*(__half2*)&u.x);
        float2 f1 = __half22float2(*(__half2*)&u.y);
        float2 f2 = __half22float2(*(__half2*)&u.z);
        float2 f3 = __half22float2(*(__half2*)&u.w);
        float a[8] = {f0.x, f0.y, f1.x, f1.y, f2.x, f2.y, f3.x, f3.y};
        #pragma unroll
        for (int i = 0; i < 8; i++) {
            float4 wv = w[(k8 * 8 + i) * 4 + part];
            acc.x += a[i] * wv.x;
            acc.y += a[i] * wv.y;
            acc.z += a[i] * wv.z;
            acc.w += a[i] * wv.w;
        }
    }
    float sc = d_dinv[row];
    __half2 p0 = __floats2half2_rn(acc.x * sc, acc.y * sc);
    __half2 p1 = __floats2half2_rn(acc.z * sc, acc.w * sc);
    uint2 u;
    u.x = *(unsigned*)&p0;
    u.y = *(unsigned*)&p1;
    *(uint2*)(d_g2 + row * 16 + part * 4) = u;
}

// ---------------- Layer 2 aggregation + final output ----------------

__global__ __launch_bounds__(256) void k_agg2(const float* __restrict__ b2,
                                              float* __restrict__ out, int n) {
    int t = blockIdx.x * blockDim.x + threadIdx.x;
    int row = t >> 2;
    int part = t & 3;
    if (row >= n) return;
    float4 acc = ld_g2h(row, part);
    int e = d_rowptr[row], end = e + d_counts[row];
    for (; e + 4 <= end; e += 4) {
        int s0 = d_col[e], s1 = d_col[e + 1], s2 = d_col[e + 2], s3 = d_col[e + 3];
        float4 v0 = ld_g2h(s0, part);
        float4 v1 = ld_g2h(s1, part);
        float4 v2 = ld_g2h(s2, part);
        float4 v3 = ld_g2h(s3, part);
        acc.x += (v0.x + v1.x) + (v2.x + v3.x);
        acc.y += (v0.y + v1.y) + (v2.y + v3.y);
        acc.z += (v0.z + v1.z) + (v2.z + v3.z);
        acc.w += (v0.w + v1.w) + (v2.w + v3.w);
    }
    for (; e < end; e++) {
        float4 v = ld_g2h(d_col[e], part);
        acc.x += v.x; acc.y += v.y; acc.z += v.z; acc.w += v.w;
    }
    float sc = d_dinv[row];
    float4 bb = ((const float4*)b2)[part];
    float4 o;
    o.x = fmaf(sc, acc.x, bb.x);
    o.y = fmaf(sc, acc.y, bb.y);
    o.z = fmaf(sc, acc.z, bb.z);
    o.w = fmaf(sc, acc.w, bb.w);
    *(float4*)&out[row * 16 + part * 4] = o;
}

// ---------------- launch: fork k_fill || k_gemm1 ----------------

extern "C" void kernel_launch(void* const* d_in, const int* in_sizes, int n_in,
                              void* d_out, int out_size) {
    const float* x  = (const float*)d_in[0];
    const void*  ei = d_in[1];
    const float* W1 = (const float*)d_in[2];
    const float* b1 = (const float*)d_in[3];
    const float* W2 = (const float*)d_in[4];
    const float* b2 = (const float*)d_in[5];
    float* out = (float*)d_out;

    int n = in_sizes[0] / 256;
    int e = in_sizes[1] / 2;
    int nv = (e + 3) / 4;

    cudaStream_t s2;
    cudaStreamCreateWithFlags(&s2, cudaStreamNonBlocking);
    cudaEvent_t ev_fork, ev_join;
    cudaEventCreateWithFlags(&ev_fork, cudaEventDisableTiming);
    cudaEventCreateWithFlags(&ev_join, cudaEventDisableTiming);

    k_zero <<<(n + 255) / 256, 256>>>((const unsigned*)ei, n);
    k_deg  <<<(nv + 255) / 256, 256>>>(ei, e, n);
    k_alloc<<<(n + 255) / 256, 256>>>(n);

    // fork: fill (stream 0) runs concurrently with gemm1 (s2)
    cudaEventRecord(ev_fork, 0);
    cudaStreamWaitEvent(s2, ev_fork, 0);
    k_fill <<<(nv + 255) / 256, 256>>>(ei, e, n);
    k_gemm1_tc<<<(n + 127) / 128, 256, 0, s2>>>(x, W1, n);
    cudaEventRecord(ev_join, s2);
    cudaStreamWaitEvent(0, ev_join, 0);

    k_agg1 <<<(n * 16 + 255) / 256, 256>>>(b1, n);
    k_gemm2<<<(n * 4 + 255) / 256, 256>>>(W2, n);
    k_agg2 <<<(n * 4 + 255) / 256, 256>>>(b2, out, n);

    cudaEventDestroy(ev_fork);
    cudaEventDestroy(ev_join);
    cudaStreamDestroy(s2);
}

// round 14
// speedup vs baseline: 2.3137x; 1.1750x over previous
#include <cuda_runtime.h>
#include <cuda_fp16.h>

// ---------------------------------------------------------------------------
// 2-layer GCN, pull aggregation over per-call CSR-by-dst.
//   g = (h @ W) * dinv[row];  agg[d] = dinv[d]*(sum_in g[src] + g[d])
// GEMM1 tf32 tensor cores; GEMM2 fp16 tensor cores (W2 -> fp16 in smem).
// g1/out1/g2 fp16 (fp32 accumulate). CSR rank trick (atomic-free fill).
// k_fill || k_gemm1 on forked streams. edge_index dtype probed at runtime.
// ---------------------------------------------------------------------------

#define MAXN 100000
#define MAXE 1600000

__device__ int    d_mode;
__device__ int    d_ctr;
__device__ int    d_counts[MAXN];
__device__ int    d_rowptr[MAXN];
__device__ int    d_rank[MAXE];
__device__ int    d_col[MAXE];
__device__ float  d_dinv[MAXN];
__device__ __half d_g1[MAXN * 128];    // (x@W1)*dinv, fp16
__device__ __half d_out1[MAXN * 128];  // relu(layer1), fp16
__device__ __half d_g2[MAXN * 16];     // (out1@W2)*dinv, fp16

// ---------------- zero + dtype probe (fused) ----------------

__global__ void k_zero(const unsigned* __restrict__ ei_w, int n) {
    int i = blockIdx.x * blockDim.x + threadIdx.x;
    if (i < n) d_counts[i] = 0;
    if (i == 0) d_ctr = 0;
    if (blockIdx.x == 0 && threadIdx.x < 32) {
        int l = threadIdx.x;
        unsigned any = 0;
        #pragma unroll
        for (int j = 0; j < 8; j++) any |= ei_w[2 * (l + j * 32) + 1];
        unsigned ball = __ballot_sync(0xFFFFFFFFu, any != 0);
        if (l == 0) d_mode = (ball == 0) ? 1 : 0;
    }
}

__device__ __forceinline__ int load_idx(const void* ei, int e, int which, int i) {
    if (d_mode) return (int)((const long long*)ei)[(long long)which * e + i];
    return ((const int*)ei)[which * e + i];
}

// ------------- degree count + per-edge rank (4 edges per thread) -----------

__global__ void k_deg(const void* __restrict__ ei, int e, int n) {
    int i4 = (blockIdx.x * blockDim.x + threadIdx.x) * 4;
    if (i4 >= e) return;
    if (d_mode == 0 && (e & 3) == 0 && i4 + 4 <= e) {
        int4 d = *(const int4*)((const int*)ei + e + i4);
        int4 r = make_int4(0, 0, 0, 0);
        if ((unsigned)d.x < (unsigned)n) r.x = atomicAdd(&d_counts[d.x], 1);
        if ((unsigned)d.y < (unsigned)n) r.y = atomicAdd(&d_counts[d.y], 1);
        if ((unsigned)d.z < (unsigned)n) r.z = atomicAdd(&d_counts[d.z], 1);
        if ((unsigned)d.w < (unsigned)n) r.w = atomicAdd(&d_counts[d.w], 1);
        *(int4*)&d_rank[i4] = r;
    } else {
        int lim = min(i4 + 4, e);
        for (int j = i4; j < lim; j++) {
            int d = load_idx(ei, e, 1, j);
            int r = 0;
            if ((unsigned)d < (unsigned)n) r = atomicAdd(&d_counts[d], 1);
            d_rank[j] = r;
        }
    }
}

// ---------------- offset allocation: block-aggregated atomic bump ----------

__global__ __launch_bounds__(256) void k_alloc(int n) {
    __shared__ int warp_base[8];
    __shared__ int block_base;
    int tid = threadIdx.x;
    int i = blockIdx.x * 256 + tid;
    int lane = tid & 31, wid = tid >> 5;

    int c = (i < n) ? d_counts[i] : 0;
    if (i < n) d_dinv[i] = rsqrtf((float)(c + 1));

    int pref = c;
    #pragma unroll
    for (int off = 1; off < 32; off <<= 1) {
        int v = __shfl_up_sync(0xFFFFFFFFu, pref, off);
        if (lane >= off) pref += v;
    }
    if (lane == 31) warp_base[wid] = pref;
    __syncthreads();
    if (tid == 0) {
        int s = 0;
        #pragma unroll
        for (int w = 0; w < 8; w++) { int t = warp_base[w]; warp_base[w] = s; s += t; }
        block_base = atomicAdd(&d_ctr, s);
    }
    __syncthreads();
    if (i < n) d_rowptr[i] = block_base + warp_base[wid] + (pref - c);
}

// ---------------- CSR fill: atomic-free via precomputed ranks ----------------

__global__ void k_fill(const void* __restrict__ ei, int e, int n) {
    int i4 = (blockIdx.x * blockDim.x + threadIdx.x) * 4;
    if (i4 >= e) return;
    if (d_mode == 0 && (e & 3) == 0 && i4 + 4 <= e) {
        int4 s = *(const int4*)((const int*)ei + i4);
        int4 d = *(const int4*)((const int*)ei + e + i4);
        int4 r = *(const int4*)&d_rank[i4];
        if ((unsigned)d.x < (unsigned)n && (unsigned)s.x < (unsigned)n)
            d_col[d_rowptr[d.x] + r.x] = s.x;
        if ((unsigned)d.y < (unsigned)n && (unsigned)s.y < (unsigned)n)
            d_col[d_rowptr[d.y] + r.y] = s.y;
        if ((unsigned)d.z < (unsigned)n && (unsigned)s.z < (unsigned)n)
            d_col[d_rowptr[d.z] + r.z] = s.z;
        if ((unsigned)d.w < (unsigned)n && (unsigned)s.w < (unsigned)n)
            d_col[d_rowptr[d.w] + r.w] = s.w;
    } else {
        int lim = min(i4 + 4, e);
        for (int j = i4; j < lim; j++) {
            int s = load_idx(ei, e, 0, j);
            int d = load_idx(ei, e, 1, j);
            if ((unsigned)d < (unsigned)n && (unsigned)s < (unsigned)n)
                d_col[d_rowptr[d] + d_rank[j]] = s;
        }
    }
}

// ---------------- Layer 1 GEMM (tf32 tensor cores) ----------------

__device__ __forceinline__ unsigned f2tf(float f) {
    unsigned u;
    asm("cvt.rna.tf32.f32 %0, %1;" : "=r"(u) : "f"(f));
    return u;
}

__device__ __forceinline__ void mma_tf32(float* d, const unsigned* a, const unsigned* b) {
    asm volatile(
        "mma.sync.aligned.m16n8k8.row.col.f32.tf32.tf32.f32 "
        "{%0,%1,%2,%3}, {%4,%5,%6,%7}, {%8,%9}, {%0,%1,%2,%3};"
        : "+f"(d[0]), "+f"(d[1]), "+f"(d[2]), "+f"(d[3])
        : "r"(a[0]), "r"(a[1]), "r"(a[2]), "r"(a[3]), "r"(b[0]), "r"(b[1]));
}

__device__ __forceinline__ void mma_f16(float* d, const unsigned* a, const unsigned* b) {
    asm volatile(
        "mma.sync.aligned.m16n8k16.row.col.f32.f16.f16.f32 "
        "{%0,%1,%2,%3}, {%4,%5,%6,%7}, {%8,%9}, {%0,%1,%2,%3};"
        : "+f"(d[0]), "+f"(d[1]), "+f"(d[2]), "+f"(d[3])
        : "r"(a[0]), "r"(a[1]), "r"(a[2]), "r"(a[3]), "r"(b[0]), "r"(b[1]));
}

__global__ __launch_bounds__(256) void k_gemm1_tc(const float* __restrict__ x,
                                                  const float* __restrict__ W1,
                                                  int n) {
    __shared__ float xs[128][36];
    __shared__ float ws[32][136];
    int tid = threadIdx.x;
    int lane = tid & 31;
    int wid = tid >> 5;
    int wm = wid & 1;
    int wn = wid >> 1;
    int row0 = blockIdx.x * 128;

    float acc[4][4][4];
    #pragma unroll
    for (int i = 0; i < 4; i++)
        #pragma unroll
        for (int j = 0; j < 4; j++)
            #pragma unroll
            for (int r = 0; r < 4; r++) acc[i][j][r] = 0.f;

    for (int k0 = 0; k0 < 256; k0 += 32) {
        if (k0) __syncthreads();
        #pragma unroll
        for (int i = 0; i < 4; i++) {
            int f = tid + i * 256;
            int r = f >> 3;
            int c = (f & 7) * 4;
            float4 v = make_float4(0.f, 0.f, 0.f, 0.f);
            if (row0 + r < n) v = *(const float4*)&x[(row0 + r) * 256 + k0 + c];
            xs[r][c] = v.x; xs[r][c + 1] = v.y; xs[r][c + 2] = v.z; xs[r][c + 3] = v.w;
        }
        #pragma unroll
        for (int i = 0; i < 4; i++) {
            int f = tid + i * 256;
            int kk = f >> 5;
            int c = (f & 31) * 4;
            float4 v = *(const float4*)&W1[(k0 + kk) * 128 + c];
            ws[kk][c] = v.x; ws[kk][c + 1] = v.y; ws[kk][c + 2] = v.z; ws[kk][c + 3] = v.w;
        }
        __syncthreads();

        #pragma unroll
        for (int ks = 0; ks < 4; ks++) {
            int k = ks * 8;
            unsigned a[4][4], b[4][2];
            int ar = lane >> 2;
            int ac = k + (lane & 3);
            #pragma unroll
            for (int mf = 0; mf < 4; mf++) {
                int r = wm * 64 + mf * 16 + ar;
                a[mf][0] = f2tf(xs[r][ac]);
                a[mf][1] = f2tf(xs[r + 8][ac]);
                a[mf][2] = f2tf(xs[r][ac + 4]);
                a[mf][3] = f2tf(xs[r + 8][ac + 4]);
            }
            int bc = wn * 32 + (lane >> 2);
            int br = k + (lane & 3);
            #pragma unroll
            for (int nf = 0; nf < 4; nf++) {
                b[nf][0] = f2tf(ws[br][bc + nf * 8]);
                b[nf][1] = f2tf(ws[br + 4][bc + nf * 8]);
            }
            #pragma unroll
            for (int mf = 0; mf < 4; mf++)
                #pragma unroll
                for (int nf = 0; nf < 4; nf++)
                    mma_tf32(acc[mf][nf], a[mf], b[nf]);
        }
    }

    #pragma unroll
    for (int mf = 0; mf < 4; mf++) {
        int r0 = row0 + wm * 64 + mf * 16 + (lane >> 2);
        int r1 = r0 + 8;
        float s0 = (r0 < n) ? d_dinv[r0] : 0.f;
        float s1 = (r1 < n) ? d_dinv[r1] : 0.f;
        #pragma unroll
        for (int nf = 0; nf < 4; nf++) {
            int c = wn * 32 + nf * 8 + (lane & 3) * 2;
            if (r0 < n)
                *(__half2*)&d_g1[r0 * 128 + c] =
                    __floats2half2_rn(acc[mf][nf][0] * s0, acc[mf][nf][1] * s0);
            if (r1 < n)
                *(__half2*)&d_g1[r1 * 128 + c] =
                    __floats2half2_rn(acc[mf][nf][2] * s1, acc[mf][nf][3] * s1);
        }
    }
}

// ---------------- fp16 helpers ----------------

__device__ __forceinline__ void acc_u4(float* acc, uint4 u) {
    float2 f0 = __half22float2(*(__half2*)&u.x);
    float2 f1 = __half22float2(*(__half2*)&u.y);
    float2 f2 = __half22float2(*(__half2*)&u.z);
    float2 f3 = __half22float2(*(__half2*)&u.w);
    acc[0] += f0.x; acc[1] += f0.y; acc[2] += f1.x; acc[3] += f1.y;
    acc[4] += f2.x; acc[5] += f2.y; acc[6] += f3.x; acc[7] += f3.y;
}

__device__ __forceinline__ float4 ld_g2h(int row, int part) {
    uint2 u = *(const uint2*)(d_g2 + row * 16 + part * 4);
    float2 f0 = __half22float2(*(__half2*)&u.x);
    float2 f1 = __half22float2(*(__half2*)&u.y);
    return make_float4(f0.x, f0.y, f1.x, f1.y);
}

// ---------------- Layer 1 aggregation: half-warp per node ----------------

__global__ __launch_bounds__(256) void k_agg1(const float* __restrict__ b1, int n) {
    int gw = (blockIdx.x * 256 + threadIdx.x) >> 4;
    int sl = threadIdx.x & 15;
    if (gw >= n) return;
    const __half* g1 = d_g1;
    int fo = sl * 8;

    float acc[8] = {};
    acc_u4(acc, *(const uint4*)(g1 + gw * 128 + fo));  // self-loop

    int e = d_rowptr[gw], end = e + d_counts[gw];
    for (; e + 4 <= end; e += 4) {
        int s0 = d_col[e], s1 = d_col[e + 1], s2 = d_col[e + 2], s3 = d_col[e + 3];
        uint4 u0 = *(const uint4*)(g1 + s0 * 128 + fo);
        uint4 u1 = *(const uint4*)(g1 + s1 * 128 + fo);
        uint4 u2 = *(const uint4*)(g1 + s2 * 128 + fo);
        uint4 u3 = *(const uint4*)(g1 + s3 * 128 + fo);
        acc_u4(acc, u0); acc_u4(acc, u1); acc_u4(acc, u2); acc_u4(acc, u3);
    }
    for (; e < end; e++)
        acc_u4(acc, *(const uint4*)(g1 + d_col[e] * 128 + fo));

    float sc = d_dinv[gw];
    float4 bb0 = ((const float4*)b1)[sl * 2];
    float4 bb1 = ((const float4*)b1)[sl * 2 + 1];
    float o0 = fmaxf(fmaf(sc, acc[0], bb0.x), 0.f);
    float o1 = fmaxf(fmaf(sc, acc[1], bb0.y), 0.f);
    float o2 = fmaxf(fmaf(sc, acc[2], bb0.z), 0.f);
    float o3 = fmaxf(fmaf(sc, acc[3], bb0.w), 0.f);
    float o4 = fmaxf(fmaf(sc, acc[4], bb1.x), 0.f);
    float o5 = fmaxf(fmaf(sc, acc[5], bb1.y), 0.f);
    float o6 = fmaxf(fmaf(sc, acc[6], bb1.z), 0.f);
    float o7 = fmaxf(fmaf(sc, acc[7], bb1.w), 0.f);
    __half2 p0 = __floats2half2_rn(o0, o1);
    __half2 p1 = __floats2half2_rn(o2, o3);
    __half2 p2 = __floats2half2_rn(o4, o5);
    __half2 p3 = __floats2half2_rn(o6, o7);
    uint4 u;
    u.x = *(unsigned*)&p0; u.y = *(unsigned*)&p1;
    u.z = *(unsigned*)&p2; u.w = *(unsigned*)&p3;
    *(uint4*)(d_out1 + gw * 128 + fo) = u;
}

// -------- Layer 2 GEMM on fp16 tensor cores: g2 = (out1 @ W2) * dinv --------
// Block: 128 rows, 256 threads (8 warps, 16 rows each). mma.m16n8k16.
// out1 tile staged fp16 in smem (136-half padded rows); W2 staged fp16
// transposed [16][136]. N=16 = 2 n-tiles, K=128 = 8 k-steps.

__global__ __launch_bounds__(256) void k_gemm2_tc(const float* __restrict__ W2, int n) {
    __shared__ __half hs[128][136];
    __shared__ __half w2t[16][136];
    int tid = threadIdx.x;
    int lane = tid & 31;
    int wid = tid >> 5;
    int row0 = blockIdx.x * 128;

    // stage out1 tile: 2048 uint4, 8 per thread
    #pragma unroll
    for (int i = 0; i < 8; i++) {
        int f = tid + i * 256;
        int r = f >> 4;
        int ch = (f & 15) * 8;
        uint4 v = make_uint4(0, 0, 0, 0);
        if (row0 + r < n) v = *(const uint4*)(d_out1 + (row0 + r) * 128 + ch);
        *(uint4*)&hs[r][ch] = v;
    }
    // stage W2 transposed fp16: 2048 entries, 8 per thread
    #pragma unroll
    for (int i = 0; i < 8; i++) {
        int idx = tid + i * 256;
        int nn = idx >> 7;
        int kk = idx & 127;
        w2t[nn][kk] = __float2half_rn(W2[kk * 16 + nn]);
    }
    __syncthreads();

    int m0 = wid * 16;
    int ar = lane >> 2;
    int ac = (lane & 3) * 2;
    float c[2][4] = {};

    #pragma unroll
    for (int ks = 0; ks < 8; ks++) {
        int k = ks * 16;
        unsigned a[4];
        a[0] = *(unsigned*)&hs[m0 + ar][k + ac];
        a[1] = *(unsigned*)&hs[m0 + ar + 8][k + ac];
        a[2] = *(unsigned*)&hs[m0 + ar][k + ac + 8];
        a[3] = *(unsigned*)&hs[m0 + ar + 8][k + ac + 8];
        #pragma unroll
        for (int nt = 0; nt < 2; nt++) {
            unsigned b[2];
            int nn = nt * 8 + (lane >> 2);
            b[0] = *(unsigned*)&w2t[nn][k + ac];
            b[1] = *(unsigned*)&w2t[nn][k + ac + 8];
            mma_f16(c[nt], a, b);
        }
    }

    int r0 = row0 + m0 + ar;
    int r1 = r0 + 8;
    float s0 = (r0 < n) ? d_dinv[r0] : 0.f;
    float s1 = (r1 < n) ? d_dinv[r1] : 0.f;
    #pragma unroll
    for (int nt = 0; nt < 2; nt++) {
        int cb = nt * 8 + ac;
        if (r0 < n)
            *(__half2*)&d_g2[r0 * 16 + cb] = __floats2half2_rn(c[nt][0] * s0, c[nt][1] * s0);
        if (r1 < n)
            *(__half2*)&d_g2[r1 * 16 + cb] = __floats2half2_rn(c[nt][2] * s1, c[nt][3] * s1);
    }
}

// ---------------- Layer 2 aggregation + final output (unroll 8) ------------

__global__ __launch_bounds__(256) void k_agg2(const float* __restrict__ b2,
                                              float* __restrict__ out, int n) {
    int t = blockIdx.x * blockDim.x + threadIdx.x;
    int row = t >> 2;
    int part = t & 3;
    if (row >= n) return;
    float4 acc = ld_g2h(row, part);
    int e = d_rowptr[row], end = e + d_counts[row];
    for (; e + 8 <= end; e += 8) {
        int s0 = d_col[e],     s1 = d_col[e + 1], s2 = d_col[e + 2], s3 = d_col[e + 3];
        int s4 = d_col[e + 4], s5 = d_col[e + 5], s6 = d_col[e + 6], s7 = d_col[e + 7];
        float4 v0 = ld_g2h(s0, part);
        float4 v1 = ld_g2h(s1, part);
        float4 v2 = ld_g2h(s2, part);
        float4 v3 = ld_g2h(s3, part);
        float4 v4 = ld_g2h(s4, part);
        float4 v5 = ld_g2h(s5, part);
        float4 v6 = ld_g2h(s6, part);
        float4 v7 = ld_g2h(s7, part);
        acc.x += ((v0.x + v1.x) + (v2.x + v3.x)) + ((v4.x + v5.x) + (v6.x + v7.x));
        acc.y += ((v0.y + v1.y) + (v2.y + v3.y)) + ((v4.y + v5.y) + (v6.y + v7.y));
        acc.z += ((v0.z + v1.z) + (v2.z + v3.z)) + ((v4.z + v5.z) + (v6.z + v7.z));
        acc.w += ((v0.w + v1.w) + (v2.w + v3.w)) + ((v4.w + v5.w) + (v6.w + v7.w));
    }
    for (; e < end; e++) {
        float4 v = ld_g2h(d_col[e], part);
        acc.x += v.x; acc.y += v.y; acc.z += v.z; acc.w += v.w;
    }
    float sc = d_dinv[row];
    float4 bb = ((const float4*)b2)[part];
    float4 o;
    o.x = fmaf(sc, acc.x, bb.x);
    o.y = fmaf(sc, acc.y, bb.y);
    o.z = fmaf(sc, acc.z, bb.z);
    o.w = fmaf(sc, acc.w, bb.w);
    *(float4*)&out[row * 16 + part * 4] = o;
}

// ---------------- launch: fork k_fill || k_gemm1 ----------------

extern "C" void kernel_launch(void* const* d_in, const int* in_sizes, int n_in,
                              void* d_out, int out_size) {
    const float* x  = (const float*)d_in[0];
    const void*  ei = d_in[1];
    const float* W1 = (const float*)d_in[2];
    const float* b1 = (const float*)d_in[3];
    const float* W2 = (const float*)d_in[4];
    const float* b2 = (const float*)d_in[5];
    float* out = (float*)d_out;

    int n = in_sizes[0] / 256;
    int e = in_sizes[1] / 2;
    int nv = (e + 3) / 4;

    cudaStream_t s2;
    cudaStreamCreateWithFlags(&s2, cudaStreamNonBlocking);
    cudaEvent_t ev_fork, ev_join;
    cudaEventCreateWithFlags(&ev_fork, cudaEventDisableTiming);
    cudaEventCreateWithFlags(&ev_join, cudaEventDisableTiming);

    k_zero <<<(n + 255) / 256, 256>>>((const unsigned*)ei, n);
    k_deg  <<<(nv + 255) / 256, 256>>>(ei, e, n);
    k_alloc<<<(n + 255) / 256, 256>>>(n);

    cudaEventRecord(ev_fork, 0);
    cudaStreamWaitEvent(s2, ev_fork, 0);
    k_fill <<<(nv + 255) / 256, 256>>>(ei, e, n);
    k_gemm1_tc<<<(n + 127) / 128, 256, 0, s2>>>(x, W1, n);
    cudaEventRecord(ev_join, s2);
    cudaStreamWaitEvent(0, ev_join, 0);

    k_agg1 <<<(n * 16 + 255) / 256, 256>>>(b1, n);
    k_gemm2_tc<<<(n + 127) / 128, 256>>>(W2, n);
    k_agg2 <<<(n * 4 + 255) / 256, 256>>>(b2, out, n);

    cudaEventDestroy(ev_fork);
    cudaEventDestroy(ev_join);
    cudaStreamDestroy(s2);
}